// round 2
// baseline (speedup 1.0000x reference)
#include <cuda_runtime.h>
#include <cuda_bf16.h>
#include <cstdint>

// Problem constants
#define BATCH 4
#define SEQ 2048
#define DMODEL 1024
#define NHEADS 16
#define HDIM 64
#define MROWS (BATCH * SEQ)        // 8192
#define QKV_N (3 * DMODEL)         // 3072

// Scratch (alloc-free rule: __device__ globals)
__device__ float g_Q[BATCH * NHEADS * SEQ * HDIM];   // [b,h,s,hd]
__device__ float g_K[BATCH * NHEADS * SEQ * HDIM];
__device__ float g_V[BATCH * NHEADS * SEQ * HDIM];
__device__ float g_O[MROWS * DMODEL];                // [b,s,D] attention output

// ---------------------------------------------------------------------------
// SGEMM: C[M,N] = A[M,K] * B[N,K]^T  (both operands K-major, bias-free Linear)
// 128x128 tile, BK=8, 256 threads, 8x8 micro-tile.
// MODE 0: plain store to C.  MODE 1: scatter into g_Q/g_K/g_V ([b,h,s,hd]).
// ---------------------------------------------------------------------------
#define BM 128
#define BN 128
#define BK 8

template <int MODE>
__global__ __launch_bounds__(256)
void sgemm_kernel(const float* __restrict__ A, const float* __restrict__ B,
                  float* __restrict__ C, int M, int N, int K)
{
    __shared__ float As[BK][BM];
    __shared__ float Bs[BK][BN];

    const int tid = threadIdx.x;
    const int tx = tid & 15;
    const int ty = tid >> 4;
    const int m0 = blockIdx.y * BM;
    const int n0 = blockIdx.x * BN;

    const int arow = tid >> 1;       // 0..127
    const int ac4  = tid & 1;        // 0..1 (which float4 within BK=8)

    const float* Aptr = A + (size_t)(m0 + arow) * K + ac4 * 4;
    const float* Bptr = B + (size_t)(n0 + arow) * K + ac4 * 4;

    float acc[8][8];
#pragma unroll
    for (int i = 0; i < 8; i++)
#pragma unroll
        for (int j = 0; j < 8; j++) acc[i][j] = 0.f;

    for (int kk = 0; kk < K; kk += BK) {
        float4 av = *(const float4*)(Aptr + kk);
        float4 bv = *(const float4*)(Bptr + kk);

        As[ac4 * 4 + 0][arow] = av.x;
        As[ac4 * 4 + 1][arow] = av.y;
        As[ac4 * 4 + 2][arow] = av.z;
        As[ac4 * 4 + 3][arow] = av.w;
        Bs[ac4 * 4 + 0][arow] = bv.x;
        Bs[ac4 * 4 + 1][arow] = bv.y;
        Bs[ac4 * 4 + 2][arow] = bv.z;
        Bs[ac4 * 4 + 3][arow] = bv.w;
        __syncthreads();

#pragma unroll
        for (int k = 0; k < BK; k++) {
            float a[8], b[8];
            *(float4*)(a)     = *(const float4*)&As[k][ty * 8];
            *(float4*)(a + 4) = *(const float4*)&As[k][ty * 8 + 4];
            *(float4*)(b)     = *(const float4*)&Bs[k][tx * 8];
            *(float4*)(b + 4) = *(const float4*)&Bs[k][tx * 8 + 4];
#pragma unroll
            for (int i = 0; i < 8; i++)
#pragma unroll
                for (int j = 0; j < 8; j++)
                    acc[i][j] = fmaf(a[i], b[j], acc[i][j]);
        }
        __syncthreads();
    }

    if (MODE == 0) {
#pragma unroll
        for (int i = 0; i < 8; i++) {
            const int m = m0 + ty * 8 + i;
            float* crow = C + (size_t)m * N + n0 + tx * 8;
            float4 v0 = make_float4(acc[i][0], acc[i][1], acc[i][2], acc[i][3]);
            float4 v1 = make_float4(acc[i][4], acc[i][5], acc[i][6], acc[i][7]);
            *(float4*)(crow)     = v0;
            *(float4*)(crow + 4) = v1;
        }
    } else {
        // scatter QKV: n in [0,3072): which = n/1024, head = (n%1024)/64, c = n%64
#pragma unroll
        for (int i = 0; i < 8; i++) {
            const int m = m0 + ty * 8 + i;
            const int b_ = m >> 11;          // /2048
            const int s_ = m & 2047;
#pragma unroll
            for (int j = 0; j < 8; j++) {
                const int n = n0 + tx * 8 + j;
                const int which = n >> 10;
                const int dd = n & 1023;
                const int h = dd >> 6;
                const int c = dd & 63;
                float* dst = (which == 0) ? g_Q : (which == 1) ? g_K : g_V;
                dst[(((size_t)(b_ * NHEADS + h)) * SEQ + s_) * HDIM + c] = acc[i][j];
            }
        }
    }
}

// ---------------------------------------------------------------------------
// Flash-style causal attention, fp32. 64x64 Q/K tiles, hd=64 resident.
// grid = (SEQ/64, BATCH*NHEADS), 256 threads, 4x4 micro-tile.
// smem budget: exactly 48KB — P tile aliases the K tile (K dead after S=QK^T).
// ---------------------------------------------------------------------------
__global__ __launch_bounds__(256)
void attn_kernel(float* __restrict__ O)
{
    const int qt = blockIdx.x;            // 0..31
    const int bh = blockIdx.y;            // 0..63
    const int b_ = bh >> 4;
    const int h  = bh & 15;
    const int q0 = qt * 64;
    const int tid = threadIdx.x;
    const int tx = tid & 15;
    const int ty = tid >> 4;
    const int rm = ty * 4;                // local q rows
    const int rn = tx * 4;                // local cols (k or d)

    __shared__ float Qs[64][64];          // [d][i]
    __shared__ float KPs[64][64];         // K as [d][j], then reused as P [i][j]
    __shared__ float Vs[64][64];          // [j][d]

    const size_t base = (size_t)bh * SEQ * HDIM;

    // Load Q tile, transposed to [d][i]
#pragma unroll
    for (int r = 0; r < 4; r++) {
        const int idx = tid + r * 256;    // float4 index in 64x64 tile
        const int row = idx >> 4;
        const int c4  = idx & 15;
        float4 v = *(const float4*)(g_Q + base + (size_t)(q0 + row) * HDIM + c4 * 4);
        Qs[c4 * 4 + 0][row] = v.x;
        Qs[c4 * 4 + 1][row] = v.y;
        Qs[c4 * 4 + 2][row] = v.z;
        Qs[c4 * 4 + 3][row] = v.w;
    }

    float m_i[4], l_i[4], o_acc[4][4];
#pragma unroll
    for (int i = 0; i < 4; i++) {
        m_i[i] = -1e30f;
        l_i[i] = 0.f;
#pragma unroll
        for (int j = 0; j < 4; j++) o_acc[i][j] = 0.f;
    }

    for (int kt = 0; kt <= qt; kt++) {
        const int k0 = kt * 64;
        __syncthreads();   // protect KPs/Vs (prev iter PV) and initial Qs load
#pragma unroll
        for (int r = 0; r < 4; r++) {
            const int idx = tid + r * 256;
            const int row = idx >> 4;
            const int c4  = idx & 15;
            float4 kv = *(const float4*)(g_K + base + (size_t)(k0 + row) * HDIM + c4 * 4);
            KPs[c4 * 4 + 0][row] = kv.x;
            KPs[c4 * 4 + 1][row] = kv.y;
            KPs[c4 * 4 + 2][row] = kv.z;
            KPs[c4 * 4 + 3][row] = kv.w;
            float4 vv = *(const float4*)(g_V + base + (size_t)(k0 + row) * HDIM + c4 * 4);
            *(float4*)&Vs[row][c4 * 4] = vv;
        }
        __syncthreads();

        // S = Q*K^T (64x64 tile)
        float s[4][4];
#pragma unroll
        for (int i = 0; i < 4; i++)
#pragma unroll
            for (int j = 0; j < 4; j++) s[i][j] = 0.f;

#pragma unroll 8
        for (int d = 0; d < 64; d++) {
            float4 a = *(const float4*)&Qs[d][rm];
            float4 b = *(const float4*)&KPs[d][rn];
            float av[4] = {a.x, a.y, a.z, a.w};
            float bv[4] = {b.x, b.y, b.z, b.w};
#pragma unroll
            for (int i = 0; i < 4; i++)
#pragma unroll
                for (int j = 0; j < 4; j++)
                    s[i][j] = fmaf(av[i], bv[j], s[i][j]);
        }

        // scale + causal mask (only diagonal tile needs the mask)
        const bool diag = (kt == qt);
#pragma unroll
        for (int i = 0; i < 4; i++)
#pragma unroll
            for (int j = 0; j < 4; j++) {
                float v = s[i][j] * 0.125f;  // 1/sqrt(64)
                if (diag && (k0 + rn + j > q0 + rm + i)) v = -1e30f;
                s[i][j] = v;
            }

        // online softmax per row, reduce across the 16 tx lanes
#pragma unroll
        for (int i = 0; i < 4; i++) {
            float mx = fmaxf(fmaxf(s[i][0], s[i][1]), fmaxf(s[i][2], s[i][3]));
#pragma unroll
            for (int off = 8; off >= 1; off >>= 1)
                mx = fmaxf(mx, __shfl_xor_sync(0xffffffffu, mx, off));
            const float m_new = fmaxf(m_i[i], mx);
            const float alpha = __expf(m_i[i] - m_new);
            float rs = 0.f;
#pragma unroll
            for (int j = 0; j < 4; j++) {
                const float p = __expf(s[i][j] - m_new);
                s[i][j] = p;
                rs += p;
            }
#pragma unroll
            for (int off = 8; off >= 1; off >>= 1)
                rs += __shfl_xor_sync(0xffffffffu, rs, off);
            l_i[i] = l_i[i] * alpha + rs;
            m_i[i] = m_new;
#pragma unroll
            for (int j = 0; j < 4; j++) o_acc[i][j] *= alpha;
        }

        // all threads done reading K from KPs -> safe to overwrite with P
        __syncthreads();
#pragma unroll
        for (int i = 0; i < 4; i++)
#pragma unroll
            for (int j = 0; j < 4; j++)
                KPs[rm + i][rn + j] = s[i][j];
        __syncthreads();

        // O += P * V
#pragma unroll 8
        for (int j = 0; j < 64; j++) {
            float pa[4];
#pragma unroll
            for (int i = 0; i < 4; i++) pa[i] = KPs[rm + i][j];
            float4 vb4 = *(const float4*)&Vs[j][rn];
            float vb[4] = {vb4.x, vb4.y, vb4.z, vb4.w};
#pragma unroll
            for (int i = 0; i < 4; i++)
#pragma unroll
                for (int jj = 0; jj < 4; jj++)
                    o_acc[i][jj] = fmaf(pa[i], vb[jj], o_acc[i][jj]);
        }
    }

    // write O_attn as [b, s, D] so the out-proj GEMM reads it K-major
#pragma unroll
    for (int i = 0; i < 4; i++) {
        const float inv = 1.f / l_i[i];
        const int s_ = q0 + rm + i;
        const size_t off = ((size_t)b_ * SEQ + s_) * DMODEL + h * HDIM + rn;
#pragma unroll
        for (int j = 0; j < 4; j++)
            O[off + j] = o_acc[i][j] * inv;
    }
}

// ---------------------------------------------------------------------------
// Launch
// ---------------------------------------------------------------------------
extern "C" void kernel_launch(void* const* d_in, const int* in_sizes, int n_in,
                              void* d_out, int out_size)
{
    const float* x     = (const float*)d_in[0];   // [4,2048,1024]
    const float* w_qkv = (const float*)d_in[1];   // [3072,1024]
    const float* w_out = (const float*)d_in[2];   // [1024,1024]
    float* out = (float*)d_out;                   // [4,2048,1024]

    float* pO = nullptr;
    cudaGetSymbolAddress((void**)&pO, g_O);

    // 1) fused QKV projection with head-layout scatter
    {
        dim3 grid(QKV_N / BN, MROWS / BM);
        sgemm_kernel<1><<<grid, 256>>>(x, w_qkv, nullptr, MROWS, QKV_N, DMODEL);
    }
    // 2) causal flash attention
    {
        dim3 grid(SEQ / 64, BATCH * NHEADS);
        attn_kernel<<<grid, 256>>>(pO);
    }
    // 3) output projection
    {
        dim3 grid(DMODEL / BN, MROWS / BM);
        sgemm_kernel<0><<<grid, 256>>>(pO, w_out, out, MROWS, DMODEL, DMODEL);
    }
}

// round 5
// speedup vs baseline: 1.4978x; 1.4978x over previous
#include <cuda_runtime.h>
#include <cuda_bf16.h>
#include <cstdint>

// ---------------------------------------------------------------------------
// Problem constants
// ---------------------------------------------------------------------------
#define BATCH 4
#define SEQ 2048
#define DMODEL 1024
#define NHEADS 16
#define HDIM 64
#define MROWS (BATCH * SEQ)        // 8192
#define QKV_N (3 * DMODEL)         // 3072
#define GK DMODEL                  // K of both GEMMs = 1024

// GEMM tiling (sm80-style mma.sync pipeline)
#define BK 32
#define NCHUNK (GK / BK)           // 32
#define TILE_BYTES 8192            // 128 rows x 32 bf16 (64B rows)
#define STAGE_BYTES (4 * TILE_BYTES)  // Ah, Al, Bh, Bl
#define STAGES 3
#define GEMM_SMEM (STAGES * STAGE_BYTES)  // 98304

// ---------------------------------------------------------------------------
// Scratch (__device__ globals; no allocs allowed)
// ---------------------------------------------------------------------------
__device__ __align__(128) float g_Q[BATCH * NHEADS * SEQ * HDIM];   // [b,h,s,hd]
__device__ __align__(128) float g_K[BATCH * NHEADS * SEQ * HDIM];
__device__ __align__(128) float g_V[BATCH * NHEADS * SEQ * HDIM];

__device__ __align__(128) __nv_bfloat16 g_xh[MROWS * DMODEL],  g_xl[MROWS * DMODEL];
__device__ __align__(128) __nv_bfloat16 g_wqh[QKV_N * DMODEL], g_wql[QKV_N * DMODEL];
__device__ __align__(128) __nv_bfloat16 g_woh[DMODEL * DMODEL], g_wol[DMODEL * DMODEL];
__device__ __align__(128) __nv_bfloat16 g_oh[MROWS * DMODEL],  g_ol[MROWS * DMODEL];

// ---------------------------------------------------------------------------
// Helpers
// ---------------------------------------------------------------------------
__device__ __forceinline__ uint32_t smem_u32(const void* p) {
    uint32_t a;
    asm("{ .reg .u64 t; cvta.to.shared.u64 t, %1; cvt.u32.u64 %0, t; }"
        : "=r"(a) : "l"(p));
    return a;
}

// SW128-style swizzle on a linear byte offset within a tile of 64B rows
#define SWZ128(o) ((o) ^ (((o) >> 3) & 0x70))

__device__ __forceinline__ void cp_async16(uint32_t s, const void* g) {
    asm volatile("cp.async.cg.shared.global [%0], [%1], 16;" :: "r"(s), "l"(g));
}
#define CP_COMMIT() asm volatile("cp.async.commit_group;" ::: "memory")
#define CP_WAIT2()  asm volatile("cp.async.wait_group 2;" ::: "memory")

__device__ __forceinline__ void ldm_x4(uint32_t* r, uint32_t addr) {
    asm volatile("ldmatrix.sync.aligned.m8n8.x4.shared.b16 {%0,%1,%2,%3}, [%4];"
                 : "=r"(r[0]), "=r"(r[1]), "=r"(r[2]), "=r"(r[3]) : "r"(addr));
}
__device__ __forceinline__ void ldm_x2(uint32_t* r, uint32_t addr) {
    asm volatile("ldmatrix.sync.aligned.m8n8.x2.shared.b16 {%0,%1}, [%2];"
                 : "=r"(r[0]), "=r"(r[1]) : "r"(addr));
}
__device__ __forceinline__ void mma_bf16(float* d, const uint32_t* a, const uint32_t* b) {
    asm volatile(
        "mma.sync.aligned.m16n8k16.row.col.f32.bf16.bf16.f32 "
        "{%0,%1,%2,%3}, {%4,%5,%6,%7}, {%8,%9}, {%0,%1,%2,%3};"
        : "+f"(d[0]), "+f"(d[1]), "+f"(d[2]), "+f"(d[3])
        : "r"(a[0]), "r"(a[1]), "r"(a[2]), "r"(a[3]), "r"(b[0]), "r"(b[1]));
}

// ---------------------------------------------------------------------------
// fp32 -> (bf16 hi, bf16 lo) split
// ---------------------------------------------------------------------------
__global__ __launch_bounds__(256)
void split_kernel(const float* __restrict__ s, __nv_bfloat16* __restrict__ h,
                  __nv_bfloat16* __restrict__ l, int n4)
{
    int i = blockIdx.x * blockDim.x + threadIdx.x;
    if (i >= n4) return;
    float4 v = ((const float4*)s)[i];
    __nv_bfloat16 h0 = __float2bfloat16(v.x);
    __nv_bfloat16 h1 = __float2bfloat16(v.y);
    __nv_bfloat16 h2 = __float2bfloat16(v.z);
    __nv_bfloat16 h3 = __float2bfloat16(v.w);
    __nv_bfloat16 l0 = __float2bfloat16(v.x - __bfloat162float(h0));
    __nv_bfloat16 l1 = __float2bfloat16(v.y - __bfloat162float(h1));
    __nv_bfloat16 l2 = __float2bfloat16(v.z - __bfloat162float(h2));
    __nv_bfloat16 l3 = __float2bfloat16(v.w - __bfloat162float(h3));
    ((__nv_bfloat162*)h)[i * 2]     = __nv_bfloat162(h0, h1);
    ((__nv_bfloat162*)h)[i * 2 + 1] = __nv_bfloat162(h2, h3);
    ((__nv_bfloat162*)l)[i * 2]     = __nv_bfloat162(l0, l1);
    ((__nv_bfloat162*)l)[i * 2 + 1] = __nv_bfloat162(l2, l3);
}

// ---------------------------------------------------------------------------
// bf16 3-term split GEMM via mma.sync: C[M,N] = A[M,K] * B[N,K]^T
// 128x128 CTA tile, BK=32, 3-stage cp.async pipeline, 8 warps (64x32 each).
// MODE 0: fp32 store to C.  MODE 1: scatter to g_Q/g_K/g_V ([b,h,s,hd]).
// ---------------------------------------------------------------------------
template <int MODE>
__global__ __launch_bounds__(256)
void mma_gemm(const __nv_bfloat16* __restrict__ Ah, const __nv_bfloat16* __restrict__ Al,
              const __nv_bfloat16* __restrict__ Bh, const __nv_bfloat16* __restrict__ Bl,
              float* __restrict__ C, int N)
{
    extern __shared__ char smem[];
    const uint32_t sb = smem_u32(smem);
    const int tid  = threadIdx.x;
    const int warp = tid >> 5;
    const int lane = tid & 31;
    const int m0 = blockIdx.y * 128;
    const int n0 = blockIdx.x * 128;
    const int wm = (warp & 1) * 64;       // warp tile: 64 (M) x 32 (N)
    const int wn = (warp >> 1) * 32;

    const __nv_bfloat16* gsrc[4] = {
        Ah + (size_t)m0 * GK, Al + (size_t)m0 * GK,
        Bh + (size_t)n0 * GK, Bl + (size_t)n0 * GK };

    auto issue = [&](int chunk, int slot) {
        const int k0 = chunk * BK;
        const uint32_t st = sb + slot * STAGE_BYTES;
#pragma unroll
        for (int t = 0; t < 4; t++) {
            const __nv_bfloat16* g = gsrc[t] + k0;
            const uint32_t tb = st + t * TILE_BYTES;
#pragma unroll
            for (int i = 0; i < 2; i++) {
                const int idx = tid * 2 + i;      // 0..511
                const int row = idx >> 2;
                const int c16 = idx & 3;
                cp_async16(tb + SWZ128(row * 64 + c16 * 16),
                           g + (size_t)row * GK + c16 * 8);
            }
        }
    };

    float acc[4][4][4];
#pragma unroll
    for (int a = 0; a < 4; a++)
#pragma unroll
        for (int b = 0; b < 4; b++)
#pragma unroll
            for (int c = 0; c < 4; c++) acc[a][b][c] = 0.f;

    issue(0, 0); CP_COMMIT();
    issue(1, 1); CP_COMMIT();

    for (int c = 0; c < NCHUNK; c++) {
        if (c + 2 < NCHUNK) issue(c + 2, (c + 2) % STAGES);
        CP_COMMIT();
        CP_WAIT2();
        __syncthreads();

        const uint32_t st = sb + (c % STAGES) * STAGE_BYTES;
        const int ta[3] = {0, 1, 0};   // Ahi, Alo, Ahi
        const int tb[3] = {2, 2, 3};   // Bhi, Bhi, Blo
#pragma unroll
        for (int p = 0; p < 3; p++) {
            const uint32_t At = st + ta[p] * TILE_BYTES;
            const uint32_t Bt = st + tb[p] * TILE_BYTES;
#pragma unroll
            for (int ks = 0; ks < 2; ks++) {
                uint32_t ar[4][4], br[4][2];
#pragma unroll
                for (int mi = 0; mi < 4; mi++) {
                    const int row = wm + mi * 16 + (lane & 15);
                    const int c16 = ks * 2 + (lane >> 4);
                    ldm_x4(ar[mi], At + SWZ128(row * 64 + c16 * 16));
                }
#pragma unroll
                for (int ni = 0; ni < 4; ni++) {
                    const int row = wn + ni * 8 + (lane & 7);
                    const int c16 = ks * 2 + ((lane >> 3) & 1);
                    ldm_x2(br[ni], Bt + SWZ128(row * 64 + c16 * 16));
                }
#pragma unroll
                for (int mi = 0; mi < 4; mi++)
#pragma unroll
                    for (int ni = 0; ni < 4; ni++)
                        mma_bf16(acc[mi][ni], ar[mi], br[ni]);
            }
        }
        __syncthreads();
    }

    // ---- epilogue straight from registers ----
#pragma unroll
    for (int mi = 0; mi < 4; mi++) {
#pragma unroll
        for (int ni = 0; ni < 4; ni++) {
            const int mA = m0 + wm + mi * 16 + (lane >> 2);
            const int n  = n0 + wn + ni * 8 + (lane & 3) * 2;
#pragma unroll
            for (int half = 0; half < 2; half++) {
                const int m = mA + half * 8;
                const float v0 = acc[mi][ni][half * 2];
                const float v1 = acc[mi][ni][half * 2 + 1];
                if (MODE == 0) {
                    *(float2*)&C[(size_t)m * N + n] = make_float2(v0, v1);
                } else {
                    const int b_ = m >> 11;
                    const int s_ = m & 2047;
                    const int which = n >> 10;
                    const int dd = n & 1023;
                    const int h = dd >> 6;
                    const int hc = dd & 63;
                    float* dst = (which == 0) ? g_Q : (which == 1) ? g_K : g_V;
                    *(float2*)&dst[(((size_t)(b_ * NHEADS + h)) * SEQ + s_) * HDIM + hc]
                        = make_float2(v0, v1);
                }
            }
        }
    }
}

// ---------------------------------------------------------------------------
// Flash-style causal attention, fp32 (proven). Epilogue writes bf16 hi/lo
// directly (input of the out-projection GEMM), skipping the fp32 round-trip.
// ---------------------------------------------------------------------------
__global__ __launch_bounds__(256)
void attn_kernel(__nv_bfloat16* __restrict__ Oh, __nv_bfloat16* __restrict__ Ol)
{
    const int qt = blockIdx.x;
    const int bh = blockIdx.y;
    const int b_ = bh >> 4;
    const int h  = bh & 15;
    const int q0 = qt * 64;
    const int tid = threadIdx.x;
    const int tx = tid & 15;
    const int ty = tid >> 4;
    const int rm = ty * 4;
    const int rn = tx * 4;

    __shared__ float Qs[64][64];
    __shared__ float KPs[64][64];
    __shared__ float Vs[64][64];

    const size_t base = (size_t)bh * SEQ * HDIM;

#pragma unroll
    for (int r = 0; r < 4; r++) {
        const int idx = tid + r * 256;
        const int row = idx >> 4;
        const int c4  = idx & 15;
        float4 v = *(const float4*)(g_Q + base + (size_t)(q0 + row) * HDIM + c4 * 4);
        Qs[c4 * 4 + 0][row] = v.x;
        Qs[c4 * 4 + 1][row] = v.y;
        Qs[c4 * 4 + 2][row] = v.z;
        Qs[c4 * 4 + 3][row] = v.w;
    }

    float m_i[4], l_i[4], o_acc[4][4];
#pragma unroll
    for (int i = 0; i < 4; i++) {
        m_i[i] = -1e30f;
        l_i[i] = 0.f;
#pragma unroll
        for (int j = 0; j < 4; j++) o_acc[i][j] = 0.f;
    }

    for (int kt = 0; kt <= qt; kt++) {
        const int k0 = kt * 64;
        __syncthreads();
#pragma unroll
        for (int r = 0; r < 4; r++) {
            const int idx = tid + r * 256;
            const int row = idx >> 4;
            const int c4  = idx & 15;
            float4 kv = *(const float4*)(g_K + base + (size_t)(k0 + row) * HDIM + c4 * 4);
            KPs[c4 * 4 + 0][row] = kv.x;
            KPs[c4 * 4 + 1][row] = kv.y;
            KPs[c4 * 4 + 2][row] = kv.z;
            KPs[c4 * 4 + 3][row] = kv.w;
            float4 vv = *(const float4*)(g_V + base + (size_t)(k0 + row) * HDIM + c4 * 4);
            *(float4*)&Vs[row][c4 * 4] = vv;
        }
        __syncthreads();

        float s[4][4];
#pragma unroll
        for (int i = 0; i < 4; i++)
#pragma unroll
            for (int j = 0; j < 4; j++) s[i][j] = 0.f;

#pragma unroll 8
        for (int d = 0; d < 64; d++) {
            float4 a = *(const float4*)&Qs[d][rm];
            float4 b = *(const float4*)&KPs[d][rn];
            float av[4] = {a.x, a.y, a.z, a.w};
            float bv[4] = {b.x, b.y, b.z, b.w};
#pragma unroll
            for (int i = 0; i < 4; i++)
#pragma unroll
                for (int j = 0; j < 4; j++)
                    s[i][j] = fmaf(av[i], bv[j], s[i][j]);
        }

        const bool diag = (kt == qt);
#pragma unroll
        for (int i = 0; i < 4; i++)
#pragma unroll
            for (int j = 0; j < 4; j++) {
                float v = s[i][j] * 0.125f;
                if (diag && (k0 + rn + j > q0 + rm + i)) v = -1e30f;
                s[i][j] = v;
            }

#pragma unroll
        for (int i = 0; i < 4; i++) {
            float mx = fmaxf(fmaxf(s[i][0], s[i][1]), fmaxf(s[i][2], s[i][3]));
#pragma unroll
            for (int off = 8; off >= 1; off >>= 1)
                mx = fmaxf(mx, __shfl_xor_sync(0xffffffffu, mx, off));
            const float m_new = fmaxf(m_i[i], mx);
            const float alpha = __expf(m_i[i] - m_new);
            float rs = 0.f;
#pragma unroll
            for (int j = 0; j < 4; j++) {
                const float p = __expf(s[i][j] - m_new);
                s[i][j] = p;
                rs += p;
            }
#pragma unroll
            for (int off = 8; off >= 1; off >>= 1)
                rs += __shfl_xor_sync(0xffffffffu, rs, off);
            l_i[i] = l_i[i] * alpha + rs;
            m_i[i] = m_new;
#pragma unroll
            for (int j = 0; j < 4; j++) o_acc[i][j] *= alpha;
        }

        __syncthreads();
#pragma unroll
        for (int i = 0; i < 4; i++)
#pragma unroll
            for (int j = 0; j < 4; j++)
                KPs[rm + i][rn + j] = s[i][j];
        __syncthreads();

#pragma unroll 8
        for (int j = 0; j < 64; j++) {
            float pa[4];
#pragma unroll
            for (int i = 0; i < 4; i++) pa[i] = KPs[rm + i][j];
            float4 vb4 = *(const float4*)&Vs[j][rn];
            float vb[4] = {vb4.x, vb4.y, vb4.z, vb4.w};
#pragma unroll
            for (int i = 0; i < 4; i++)
#pragma unroll
                for (int jj = 0; jj < 4; jj++)
                    o_acc[i][jj] = fmaf(pa[i], vb[jj], o_acc[i][jj]);
        }
    }

    // write attention out as bf16 hi/lo, [b, s, D] (K-major for out-proj)
#pragma unroll
    for (int i = 0; i < 4; i++) {
        const float inv = 1.f / l_i[i];
        const int s_ = q0 + rm + i;
        const size_t off = ((size_t)b_ * SEQ + s_) * DMODEL + h * HDIM + rn;
        __nv_bfloat16 hv[4], lv[4];
#pragma unroll
        for (int j = 0; j < 4; j++) {
            const float v = o_acc[i][j] * inv;
            hv[j] = __float2bfloat16(v);
            lv[j] = __float2bfloat16(v - __bfloat162float(hv[j]));
        }
        *(__nv_bfloat162*)&Oh[off]     = __nv_bfloat162(hv[0], hv[1]);
        *(__nv_bfloat162*)&Oh[off + 2] = __nv_bfloat162(hv[2], hv[3]);
        *(__nv_bfloat162*)&Ol[off]     = __nv_bfloat162(lv[0], lv[1]);
        *(__nv_bfloat162*)&Ol[off + 2] = __nv_bfloat162(lv[2], lv[3]);
    }
}

// ---------------------------------------------------------------------------
// Launch
// ---------------------------------------------------------------------------
extern "C" void kernel_launch(void* const* d_in, const int* in_sizes, int n_in,
                              void* d_out, int out_size)
{
    const float* x     = (const float*)d_in[0];   // [4,2048,1024]
    const float* w_qkv = (const float*)d_in[1];   // [3072,1024]
    const float* w_out = (const float*)d_in[2];   // [1024,1024]
    float* out = (float*)d_out;                   // [4,2048,1024]

    __nv_bfloat16 *pxh, *pxl, *pwqh, *pwql, *pwoh, *pwol, *poh, *pol;
    cudaGetSymbolAddress((void**)&pxh, g_xh);
    cudaGetSymbolAddress((void**)&pxl, g_xl);
    cudaGetSymbolAddress((void**)&pwqh, g_wqh);
    cudaGetSymbolAddress((void**)&pwql, g_wql);
    cudaGetSymbolAddress((void**)&pwoh, g_woh);
    cudaGetSymbolAddress((void**)&pwol, g_wol);
    cudaGetSymbolAddress((void**)&poh, g_oh);
    cudaGetSymbolAddress((void**)&pol, g_ol);

    cudaFuncSetAttribute(mma_gemm<0>, cudaFuncAttributeMaxDynamicSharedMemorySize, GEMM_SMEM);
    cudaFuncSetAttribute(mma_gemm<1>, cudaFuncAttributeMaxDynamicSharedMemorySize, GEMM_SMEM);

    // 1) bf16 hi/lo splits of x and weights
    split_kernel<<<(MROWS * DMODEL / 4 + 255) / 256, 256>>>(x, pxh, pxl, MROWS * DMODEL / 4);
    split_kernel<<<(QKV_N * DMODEL / 4 + 255) / 256, 256>>>(w_qkv, pwqh, pwql, QKV_N * DMODEL / 4);
    split_kernel<<<(DMODEL * DMODEL / 4 + 255) / 256, 256>>>(w_out, pwoh, pwol, DMODEL * DMODEL / 4);

    // 2) QKV projection (tensor cores) with [b,h,s,hd] scatter
    {
        dim3 grid(QKV_N / 128, MROWS / 128);
        mma_gemm<1><<<grid, 256, GEMM_SMEM>>>(pxh, pxl, pwqh, pwql, nullptr, QKV_N);
    }
    // 3) causal flash attention (fp32), bf16 hi/lo output
    {
        dim3 grid(SEQ / 64, BATCH * NHEADS);
        attn_kernel<<<grid, 256>>>(poh, pol);
    }
    // 4) out projection (tensor cores)
    {
        dim3 grid(DMODEL / 128, MROWS / 128);
        mma_gemm<0><<<grid, 256, GEMM_SMEM>>>(poh, pol, pwoh, pwol, out, DMODEL);
    }
}

// round 6
// speedup vs baseline: 2.7057x; 1.8064x over previous
#include <cuda_runtime.h>
#include <cuda_bf16.h>
#include <cstdint>

// ---------------------------------------------------------------------------
// Problem constants
// ---------------------------------------------------------------------------
#define BATCH 4
#define SEQ 2048
#define DMODEL 1024
#define NHEADS 16
#define HDIM 64
#define MROWS (BATCH * SEQ)        // 8192
#define QKV_N (3 * DMODEL)         // 3072
#define GK DMODEL                  // K of both GEMMs = 1024

// GEMM tiling (sm80-style mma.sync pipeline)
#define BK 32
#define NCHUNK (GK / BK)           // 32
#define TILE_BYTES 8192            // 128 rows x 32 bf16 (64B rows)
#define STAGE_BYTES (4 * TILE_BYTES)
#define STAGES 3
#define GEMM_SMEM (STAGES * STAGE_BYTES)  // 98304

// Attention smem map (dynamic): Qh 16K, Ql 16K, then 2 stages x 32K
#define AQH 0
#define AQL 16384
#define ASTG 32768
#define ASTG_B 32768               // per stage: KH 0, KL 8K, VH 16K, VL 24K
#define ATT_SMEM (ASTG + 2 * ASTG_B)   // 98304

// ---------------------------------------------------------------------------
// Scratch (__device__ globals; no allocs allowed)
// ---------------------------------------------------------------------------
#define QKV_ELEMS (BATCH * NHEADS * SEQ * HDIM)
__device__ __align__(128) __nv_bfloat16 g_qh[QKV_ELEMS], g_ql[QKV_ELEMS];   // [b,h,s,hd]
__device__ __align__(128) __nv_bfloat16 g_kh[QKV_ELEMS], g_kl[QKV_ELEMS];   // [b,h,s,hd]
__device__ __align__(128) __nv_bfloat16 g_vth[QKV_ELEMS], g_vtl[QKV_ELEMS]; // [b,h,hd,s]

__device__ __align__(128) __nv_bfloat16 g_xh[MROWS * DMODEL],  g_xl[MROWS * DMODEL];
__device__ __align__(128) __nv_bfloat16 g_wqh[QKV_N * DMODEL], g_wql[QKV_N * DMODEL];
__device__ __align__(128) __nv_bfloat16 g_woh[DMODEL * DMODEL], g_wol[DMODEL * DMODEL];
__device__ __align__(128) __nv_bfloat16 g_oh[MROWS * DMODEL],  g_ol[MROWS * DMODEL];

// ---------------------------------------------------------------------------
// Helpers
// ---------------------------------------------------------------------------
__device__ __forceinline__ uint32_t smem_u32(const void* p) {
    uint32_t a;
    asm("{ .reg .u64 t; cvta.to.shared.u64 t, %1; cvt.u32.u64 %0, t; }"
        : "=r"(a) : "l"(p));
    return a;
}

#define SWZ128(o) ((o) ^ (((o) >> 3) & 0x70))

__device__ __forceinline__ void cp_async16(uint32_t s, const void* g) {
    asm volatile("cp.async.cg.shared.global [%0], [%1], 16;" :: "r"(s), "l"(g));
}
#define CP_COMMIT() asm volatile("cp.async.commit_group;" ::: "memory")
#define CP_WAIT2()  asm volatile("cp.async.wait_group 2;" ::: "memory")
#define CP_WAIT1()  asm volatile("cp.async.wait_group 1;" ::: "memory")

__device__ __forceinline__ void ldm_x4(uint32_t* r, uint32_t addr) {
    asm volatile("ldmatrix.sync.aligned.m8n8.x4.shared.b16 {%0,%1,%2,%3}, [%4];"
                 : "=r"(r[0]), "=r"(r[1]), "=r"(r[2]), "=r"(r[3]) : "r"(addr));
}
__device__ __forceinline__ void ldm_x2(uint32_t* r, uint32_t addr) {
    asm volatile("ldmatrix.sync.aligned.m8n8.x2.shared.b16 {%0,%1}, [%2];"
                 : "=r"(r[0]), "=r"(r[1]) : "r"(addr));
}
__device__ __forceinline__ void mma_bf16(float* d, const uint32_t* a, const uint32_t* b) {
    asm volatile(
        "mma.sync.aligned.m16n8k16.row.col.f32.bf16.bf16.f32 "
        "{%0,%1,%2,%3}, {%4,%5,%6,%7}, {%8,%9}, {%0,%1,%2,%3};"
        : "+f"(d[0]), "+f"(d[1]), "+f"(d[2]), "+f"(d[3])
        : "r"(a[0]), "r"(a[1]), "r"(a[2]), "r"(a[3]), "r"(b[0]), "r"(b[1]));
}
__device__ __forceinline__ uint32_t pack_bf16(__nv_bfloat16 a, __nv_bfloat16 b) {
    __nv_bfloat162 t(a, b);
    return *(uint32_t*)&t;
}

// ---------------------------------------------------------------------------
// fp32 -> (bf16 hi, bf16 lo) split
// ---------------------------------------------------------------------------
__global__ __launch_bounds__(256)
void split_kernel(const float* __restrict__ s, __nv_bfloat16* __restrict__ h,
                  __nv_bfloat16* __restrict__ l, int n4)
{
    int i = blockIdx.x * blockDim.x + threadIdx.x;
    if (i >= n4) return;
    float4 v = ((const float4*)s)[i];
    __nv_bfloat16 h0 = __float2bfloat16(v.x);
    __nv_bfloat16 h1 = __float2bfloat16(v.y);
    __nv_bfloat16 h2 = __float2bfloat16(v.z);
    __nv_bfloat16 h3 = __float2bfloat16(v.w);
    __nv_bfloat16 l0 = __float2bfloat16(v.x - __bfloat162float(h0));
    __nv_bfloat16 l1 = __float2bfloat16(v.y - __bfloat162float(h1));
    __nv_bfloat16 l2 = __float2bfloat16(v.z - __bfloat162float(h2));
    __nv_bfloat16 l3 = __float2bfloat16(v.w - __bfloat162float(h3));
    ((__nv_bfloat162*)h)[i * 2]     = __nv_bfloat162(h0, h1);
    ((__nv_bfloat162*)h)[i * 2 + 1] = __nv_bfloat162(h2, h3);
    ((__nv_bfloat162*)l)[i * 2]     = __nv_bfloat162(l0, l1);
    ((__nv_bfloat162*)l)[i * 2 + 1] = __nv_bfloat162(l2, l3);
}

// ---------------------------------------------------------------------------
// bf16 3-term split GEMM via mma.sync: C[M,N] = A[M,K] * B[N,K]^T
// MODE 0: fp32 store to C.
// MODE 1: bf16 hi/lo scatter: Q,K -> [b,h,s,hd]; V -> transposed [b,h,hd,s].
// ---------------------------------------------------------------------------
template <int MODE>
__global__ __launch_bounds__(256)
void mma_gemm(const __nv_bfloat16* __restrict__ Ah, const __nv_bfloat16* __restrict__ Al,
              const __nv_bfloat16* __restrict__ Bh, const __nv_bfloat16* __restrict__ Bl,
              float* __restrict__ C, int N)
{
    extern __shared__ char smem[];
    const uint32_t sb = smem_u32(smem);
    const int tid  = threadIdx.x;
    const int warp = tid >> 5;
    const int lane = tid & 31;
    const int m0 = blockIdx.y * 128;
    const int n0 = blockIdx.x * 128;
    const int wm = (warp & 1) * 64;
    const int wn = (warp >> 1) * 32;

    const __nv_bfloat16* gsrc[4] = {
        Ah + (size_t)m0 * GK, Al + (size_t)m0 * GK,
        Bh + (size_t)n0 * GK, Bl + (size_t)n0 * GK };

    auto issue = [&](int chunk, int slot) {
        const int k0 = chunk * BK;
        const uint32_t st = sb + slot * STAGE_BYTES;
#pragma unroll
        for (int t = 0; t < 4; t++) {
            const __nv_bfloat16* g = gsrc[t] + k0;
            const uint32_t tb = st + t * TILE_BYTES;
#pragma unroll
            for (int i = 0; i < 2; i++) {
                const int idx = tid * 2 + i;
                const int row = idx >> 2;
                const int c16 = idx & 3;
                cp_async16(tb + SWZ128(row * 64 + c16 * 16),
                           g + (size_t)row * GK + c16 * 8);
            }
        }
    };

    float acc[4][4][4];
#pragma unroll
    for (int a = 0; a < 4; a++)
#pragma unroll
        for (int b = 0; b < 4; b++)
#pragma unroll
            for (int c = 0; c < 4; c++) acc[a][b][c] = 0.f;

    issue(0, 0); CP_COMMIT();
    issue(1, 1); CP_COMMIT();

    for (int c = 0; c < NCHUNK; c++) {
        if (c + 2 < NCHUNK) issue(c + 2, (c + 2) % STAGES);
        CP_COMMIT();
        CP_WAIT2();
        __syncthreads();

        const uint32_t st = sb + (c % STAGES) * STAGE_BYTES;
        const int ta[3] = {0, 1, 0};
        const int tb[3] = {2, 2, 3};
#pragma unroll
        for (int p = 0; p < 3; p++) {
            const uint32_t At = st + ta[p] * TILE_BYTES;
            const uint32_t Bt = st + tb[p] * TILE_BYTES;
#pragma unroll
            for (int ks = 0; ks < 2; ks++) {
                uint32_t ar[4][4], br[4][2];
#pragma unroll
                for (int mi = 0; mi < 4; mi++) {
                    const int row = wm + mi * 16 + (lane & 15);
                    const int c16 = ks * 2 + (lane >> 4);
                    ldm_x4(ar[mi], At + SWZ128(row * 64 + c16 * 16));
                }
#pragma unroll
                for (int ni = 0; ni < 4; ni++) {
                    const int row = wn + ni * 8 + (lane & 7);
                    const int c16 = ks * 2 + ((lane >> 3) & 1);
                    ldm_x2(br[ni], Bt + SWZ128(row * 64 + c16 * 16));
                }
#pragma unroll
                for (int mi = 0; mi < 4; mi++)
#pragma unroll
                    for (int ni = 0; ni < 4; ni++)
                        mma_bf16(acc[mi][ni], ar[mi], br[ni]);
            }
        }
        __syncthreads();
    }

#pragma unroll
    for (int mi = 0; mi < 4; mi++) {
#pragma unroll
        for (int ni = 0; ni < 4; ni++) {
            const int mA = m0 + wm + mi * 16 + (lane >> 2);
            const int n  = n0 + wn + ni * 8 + (lane & 3) * 2;
#pragma unroll
            for (int half = 0; half < 2; half++) {
                const int m = mA + half * 8;
                const float v0 = acc[mi][ni][half * 2];
                const float v1 = acc[mi][ni][half * 2 + 1];
                if (MODE == 0) {
                    *(float2*)&C[(size_t)m * N + n] = make_float2(v0, v1);
                } else {
                    const int b_ = m >> 11;
                    const int s_ = m & 2047;
                    const int which = n >> 10;
                    const int dd = n & 1023;
                    const int hh = dd >> 6;
                    const int hc = dd & 63;
                    __nv_bfloat16 h0 = __float2bfloat16(v0);
                    __nv_bfloat16 h1 = __float2bfloat16(v1);
                    __nv_bfloat16 L0 = __float2bfloat16(v0 - __bfloat162float(h0));
                    __nv_bfloat16 L1 = __float2bfloat16(v1 - __bfloat162float(h1));
                    if (which == 2) {
                        // V transposed: [b,h,hd,s]
                        const size_t o = ((size_t)(b_ * NHEADS + hh) * HDIM + hc) * SEQ + s_;
                        g_vth[o] = h0; g_vth[o + SEQ] = h1;
                        g_vtl[o] = L0; g_vtl[o + SEQ] = L1;
                    } else {
                        const size_t o = ((size_t)(b_ * NHEADS + hh) * SEQ + s_) * HDIM + hc;
                        __nv_bfloat16* dh = (which == 0) ? g_qh : g_kh;
                        __nv_bfloat16* dl = (which == 0) ? g_ql : g_kl;
                        *(__nv_bfloat162*)&dh[o] = __nv_bfloat162(h0, h1);
                        *(__nv_bfloat162*)&dl[o] = __nv_bfloat162(L0, L1);
                    }
                }
            }
        }
    }
}

// ---------------------------------------------------------------------------
// Causal flash attention via mma.sync, bf16 3-term split everywhere.
// CTA = 128 Q rows of one (b,h); 8 warps x 16 rows; K-tiles of 64, 2 stages.
// ---------------------------------------------------------------------------
__global__ __launch_bounds__(256)
void attn_mma(__nv_bfloat16* __restrict__ Oh, __nv_bfloat16* __restrict__ Ol)
{
    extern __shared__ char smem[];
    const uint32_t sb = smem_u32(smem);
    const int tid  = threadIdx.x;
    const int warp = tid >> 5;
    const int lane = tid & 31;
    const int qt = gridDim.x - 1 - blockIdx.x;   // big tiles first
    const int bh = blockIdx.y;
    const int b_ = bh >> 4;
    const int h  = bh & 15;
    const int q0 = qt * 128;
    const int ktmax = 2 * qt + 1;

    const size_t qkbase = (size_t)bh * SEQ * HDIM;
    const size_t vbase  = (size_t)bh * HDIM * SEQ;

    // ---- Q tiles (hi, lo): 128 x 64 bf16, 128B rows, swizzled ----
    {
        const __nv_bfloat16* src[2] = { g_qh + qkbase + (size_t)q0 * HDIM,
                                        g_ql + qkbase + (size_t)q0 * HDIM };
        const uint32_t dst[2] = { sb + AQH, sb + AQL };
#pragma unroll
        for (int t = 0; t < 2; t++)
#pragma unroll
            for (int i = 0; i < 4; i++) {
                const int idx = i * 256 + tid;      // 0..1023
                const int row = idx >> 3;
                const int c16 = idx & 7;
                cp_async16(dst[t] + SWZ128(row * 128 + c16 * 16),
                           src[t] + (size_t)row * HDIM + c16 * 8);
            }
        CP_COMMIT();
    }

    auto issue_kv = [&](int kt, int stg) {
        const uint32_t s0 = sb + ASTG + stg * ASTG_B;
        const __nv_bfloat16* ksrc[2] = { g_kh + qkbase + (size_t)kt * 64 * HDIM,
                                         g_kl + qkbase + (size_t)kt * 64 * HDIM };
#pragma unroll
        for (int t = 0; t < 2; t++)
#pragma unroll
            for (int i = 0; i < 2; i++) {
                const int idx = i * 256 + tid;      // 0..511
                const int row = idx >> 3;
                const int c16 = idx & 7;
                cp_async16(s0 + t * 8192 + SWZ128(row * 128 + c16 * 16),
                           ksrc[t] + (size_t)row * HDIM + c16 * 8);
            }
        const __nv_bfloat16* vsrc[2] = { g_vth + vbase + kt * 64,
                                         g_vtl + vbase + kt * 64 };
#pragma unroll
        for (int t = 0; t < 2; t++)
#pragma unroll
            for (int i = 0; i < 2; i++) {
                const int idx = i * 256 + tid;
                const int row = idx >> 3;           // hd row
                const int c16 = idx & 7;
                cp_async16(s0 + 16384 + t * 8192 + SWZ128(row * 128 + c16 * 16),
                           vsrc[t] + (size_t)row * SEQ + c16 * 8);
            }
    };

    issue_kv(0, 0); CP_COMMIT();
    CP_WAIT1();          // Q done (kv0 may be in flight)
    __syncthreads();

    // Q fragments, all 4 k-steps, hi & lo (Q is fixed for the whole CTA)
    uint32_t qfh[4][4], qfl[4][4];
    const int arow = warp * 16 + (lane & 15);
#pragma unroll
    for (int ks = 0; ks < 4; ks++) {
        const int c16 = ks * 2 + (lane >> 4);
        ldm_x4(qfh[ks], sb + AQH + SWZ128(arow * 128 + c16 * 16));
        ldm_x4(qfl[ks], sb + AQL + SWZ128(arow * 128 + c16 * 16));
    }

    float m_i[2] = {-1e30f, -1e30f}, l_i[2] = {0.f, 0.f};
    float o[8][4];
#pragma unroll
    for (int nt = 0; nt < 8; nt++)
#pragma unroll
        for (int c = 0; c < 4; c++) o[nt][c] = 0.f;

    const int r0 = lane >> 2;            // row within warp tile (and +8)
    const int cc = (lane & 3) * 2;       // col pair base

    for (int kt = 0; kt <= ktmax; kt++) {
        __syncthreads();                 // everyone done with buffer (kt+1)&1
        if (kt < ktmax) issue_kv(kt + 1, (kt + 1) & 1);
        CP_COMMIT();
        CP_WAIT1();
        __syncthreads();

        // per-warp fully-masked tile skip (barriers above/below still uniform)
        if (kt * 64 > q0 + warp * 16 + 15) continue;

        const uint32_t s0 = sb + ASTG + (kt & 1) * ASTG_B;

        // ---- S = Q K^T (3-term) ----
        float s[8][4];
#pragma unroll
        for (int nt = 0; nt < 8; nt++)
#pragma unroll
            for (int c = 0; c < 4; c++) s[nt][c] = 0.f;

#pragma unroll
        for (int ks = 0; ks < 4; ks++) {
            uint32_t bkh[8][2], bkl[8][2];
            const int c16 = ks * 2 + ((lane >> 3) & 1);
#pragma unroll
            for (int nt = 0; nt < 8; nt++) {
                const int row = nt * 8 + (lane & 7);
                ldm_x2(bkh[nt], s0 + SWZ128(row * 128 + c16 * 16));
                ldm_x2(bkl[nt], s0 + 8192 + SWZ128(row * 128 + c16 * 16));
            }
#pragma unroll
            for (int nt = 0; nt < 8; nt++) {
                mma_bf16(s[nt], qfh[ks], bkh[nt]);
                mma_bf16(s[nt], qfl[ks], bkh[nt]);
                mma_bf16(s[nt], qfh[ks], bkl[nt]);
            }
        }

        // ---- scale + causal mask ----
        const bool needmask = (kt * 64 + 63 > q0 + warp * 16);
#pragma unroll
        for (int nt = 0; nt < 8; nt++)
#pragma unroll
            for (int c = 0; c < 4; c++) {
                float v = s[nt][c] * 0.125f;
                if (needmask) {
                    const int gq = q0 + warp * 16 + r0 + ((c >> 1) ? 8 : 0);
                    const int gk = kt * 64 + nt * 8 + cc + (c & 1);
                    if (gk > gq) v = -1e30f;
                }
                s[nt][c] = v;
            }

        // ---- online softmax (2 rows per thread) ----
#pragma unroll
        for (int hf = 0; hf < 2; hf++) {
            float mx = -1e30f;
#pragma unroll
            for (int nt = 0; nt < 8; nt++)
                mx = fmaxf(mx, fmaxf(s[nt][hf * 2], s[nt][hf * 2 + 1]));
            mx = fmaxf(mx, __shfl_xor_sync(0xffffffffu, mx, 1));
            mx = fmaxf(mx, __shfl_xor_sync(0xffffffffu, mx, 2));
            const float mnew = fmaxf(m_i[hf], mx);
            const float alpha = __expf(m_i[hf] - mnew);
            float rs = 0.f;
#pragma unroll
            for (int nt = 0; nt < 8; nt++) {
                const float p0 = __expf(s[nt][hf * 2]     - mnew);
                const float p1 = __expf(s[nt][hf * 2 + 1] - mnew);
                s[nt][hf * 2] = p0; s[nt][hf * 2 + 1] = p1;
                rs += p0 + p1;
            }
            rs += __shfl_xor_sync(0xffffffffu, rs, 1);
            rs += __shfl_xor_sync(0xffffffffu, rs, 2);
            l_i[hf] = l_i[hf] * alpha + rs;
            m_i[hf] = mnew;
#pragma unroll
            for (int nt = 0; nt < 8; nt++) {
                o[nt][hf * 2] *= alpha; o[nt][hf * 2 + 1] *= alpha;
            }
        }

        // ---- O += P V (P hi/lo in regs; V^T tiles) ----
#pragma unroll
        for (int j = 0; j < 4; j++) {
            uint32_t ah[4], al[4];
#pragma unroll
            for (int half = 0; half < 2; half++) {
                const float p0 = s[2 * j + half][0], p1 = s[2 * j + half][1];
                const float p2 = s[2 * j + half][2], p3 = s[2 * j + half][3];
                const __nv_bfloat16 h0 = __float2bfloat16(p0), h1 = __float2bfloat16(p1);
                const __nv_bfloat16 h2 = __float2bfloat16(p2), h3 = __float2bfloat16(p3);
                ah[half * 2]     = pack_bf16(h0, h1);
                ah[half * 2 + 1] = pack_bf16(h2, h3);
                al[half * 2]     = pack_bf16(__float2bfloat16(p0 - __bfloat162float(h0)),
                                             __float2bfloat16(p1 - __bfloat162float(h1)));
                al[half * 2 + 1] = pack_bf16(__float2bfloat16(p2 - __bfloat162float(h2)),
                                             __float2bfloat16(p3 - __bfloat162float(h3)));
            }
            const int c16 = j * 2 + ((lane >> 3) & 1);
#pragma unroll
            for (int nt = 0; nt < 8; nt++) {
                const int row = nt * 8 + (lane & 7);
                uint32_t vh[2], vl[2];
                ldm_x2(vh, s0 + 16384 + SWZ128(row * 128 + c16 * 16));
                ldm_x2(vl, s0 + 24576 + SWZ128(row * 128 + c16 * 16));
                mma_bf16(o[nt], ah, vh);
                mma_bf16(o[nt], al, vh);
                mma_bf16(o[nt], ah, vl);
            }
        }
    }

    // ---- epilogue: bf16 hi/lo into [b,s,D] ----
#pragma unroll
    for (int hf = 0; hf < 2; hf++) {
        const float inv = 1.f / l_i[hf];
        const int gq = q0 + warp * 16 + r0 + hf * 8;
        const size_t off = ((size_t)b_ * SEQ + gq) * DMODEL + h * HDIM + cc;
#pragma unroll
        for (int nt = 0; nt < 8; nt++) {
            const float v0 = o[nt][hf * 2] * inv;
            const float v1 = o[nt][hf * 2 + 1] * inv;
            const __nv_bfloat16 h0 = __float2bfloat16(v0);
            const __nv_bfloat16 h1 = __float2bfloat16(v1);
            *(__nv_bfloat162*)&Oh[off + nt * 8] = __nv_bfloat162(h0, h1);
            *(__nv_bfloat162*)&Ol[off + nt * 8] =
                __nv_bfloat162(__float2bfloat16(v0 - __bfloat162float(h0)),
                               __float2bfloat16(v1 - __bfloat162float(h1)));
        }
    }
}

// ---------------------------------------------------------------------------
// Launch
// ---------------------------------------------------------------------------
extern "C" void kernel_launch(void* const* d_in, const int* in_sizes, int n_in,
                              void* d_out, int out_size)
{
    const float* x     = (const float*)d_in[0];
    const float* w_qkv = (const float*)d_in[1];
    const float* w_out = (const float*)d_in[2];
    float* out = (float*)d_out;

    __nv_bfloat16 *pxh, *pxl, *pwqh, *pwql, *pwoh, *pwol, *poh, *pol;
    cudaGetSymbolAddress((void**)&pxh, g_xh);
    cudaGetSymbolAddress((void**)&pxl, g_xl);
    cudaGetSymbolAddress((void**)&pwqh, g_wqh);
    cudaGetSymbolAddress((void**)&pwql, g_wql);
    cudaGetSymbolAddress((void**)&pwoh, g_woh);
    cudaGetSymbolAddress((void**)&pwol, g_wol);
    cudaGetSymbolAddress((void**)&poh, g_oh);
    cudaGetSymbolAddress((void**)&pol, g_ol);

    cudaFuncSetAttribute(mma_gemm<0>, cudaFuncAttributeMaxDynamicSharedMemorySize, GEMM_SMEM);
    cudaFuncSetAttribute(mma_gemm<1>, cudaFuncAttributeMaxDynamicSharedMemorySize, GEMM_SMEM);
    cudaFuncSetAttribute(attn_mma,    cudaFuncAttributeMaxDynamicSharedMemorySize, ATT_SMEM);

    // 1) bf16 hi/lo splits
    split_kernel<<<(MROWS * DMODEL / 4 + 255) / 256, 256>>>(x, pxh, pxl, MROWS * DMODEL / 4);
    split_kernel<<<(QKV_N * DMODEL / 4 + 255) / 256, 256>>>(w_qkv, pwqh, pwql, QKV_N * DMODEL / 4);
    split_kernel<<<(DMODEL * DMODEL / 4 + 255) / 256, 256>>>(w_out, pwoh, pwol, DMODEL * DMODEL / 4);

    // 2) QKV projection -> bf16 hi/lo Q,K,V^T in head layout
    {
        dim3 grid(QKV_N / 128, MROWS / 128);
        mma_gemm<1><<<grid, 256, GEMM_SMEM>>>(pxh, pxl, pwqh, pwql, nullptr, QKV_N);
    }
    // 3) causal flash attention (tensor cores)
    {
        dim3 grid(SEQ / 128, BATCH * NHEADS);
        attn_mma<<<grid, 256, ATT_SMEM>>>(poh, pol);
    }
    // 4) out projection
    {
        dim3 grid(DMODEL / 128, MROWS / 128);
        mma_gemm<0><<<grid, 256, GEMM_SMEM>>>(poh, pol, pwoh, pwol, out, DMODEL);
    }
}

// round 7
// speedup vs baseline: 3.4532x; 1.2763x over previous
#include <cuda_runtime.h>
#include <cuda_bf16.h>
#include <cstdint>

// ---------------------------------------------------------------------------
// Problem constants
// ---------------------------------------------------------------------------
#define BATCH 4
#define SEQ 2048
#define DMODEL 1024
#define NHEADS 16
#define HDIM 64
#define MROWS (BATCH * SEQ)        // 8192
#define QKV_N (3 * DMODEL)         // 3072
#define GK DMODEL                  // K of both GEMMs = 1024

// GEMM tiling (sm80-style mma.sync pipeline)
#define BK 64
#define NCHUNK (GK / BK)           // 16
#define TILE_BYTES 16384           // 128 rows x 64 bf16 (128B rows)
#define STAGE_BYTES (4 * TILE_BYTES)   // Ah, Al, Bh, Bl = 64KB
#define STAGES 2
#define GEMM_SMEM (STAGES * STAGE_BYTES)  // 131072

// Attention smem map (dynamic): Qh 16K, Ql 16K, then 2 stages x 32K
#define AQH 0
#define AQL 16384
#define ASTG 32768
#define ASTG_B 32768               // per stage: KH 0, KL 8K, VH 16K, VL 24K
#define ATT_SMEM (ASTG + 2 * ASTG_B)   // 98304

// V-transpose staging pitch (elements)
#define VPITCH 136

// ---------------------------------------------------------------------------
// Scratch (__device__ globals; no allocs allowed)
// ---------------------------------------------------------------------------
#define QKV_ELEMS (BATCH * NHEADS * SEQ * HDIM)
__device__ __align__(128) __nv_bfloat16 g_qh[QKV_ELEMS], g_ql[QKV_ELEMS];   // [b,h,s,hd]
__device__ __align__(128) __nv_bfloat16 g_kh[QKV_ELEMS], g_kl[QKV_ELEMS];   // [b,h,s,hd]
__device__ __align__(128) __nv_bfloat16 g_vth[QKV_ELEMS], g_vtl[QKV_ELEMS]; // [b,h,hd,s]

__device__ __align__(128) __nv_bfloat16 g_xh[MROWS * DMODEL],  g_xl[MROWS * DMODEL];
__device__ __align__(128) __nv_bfloat16 g_wqh[QKV_N * DMODEL], g_wql[QKV_N * DMODEL];
__device__ __align__(128) __nv_bfloat16 g_woh[DMODEL * DMODEL], g_wol[DMODEL * DMODEL];
__device__ __align__(128) __nv_bfloat16 g_oh[MROWS * DMODEL],  g_ol[MROWS * DMODEL];

// ---------------------------------------------------------------------------
// Helpers
// ---------------------------------------------------------------------------
__device__ __forceinline__ uint32_t smem_u32(const void* p) {
    uint32_t a;
    asm("{ .reg .u64 t; cvta.to.shared.u64 t, %1; cvt.u32.u64 %0, t; }"
        : "=r"(a) : "l"(p));
    return a;
}

#define SWZ128(o) ((o) ^ (((o) >> 3) & 0x70))

__device__ __forceinline__ void cp_async16(uint32_t s, const void* g) {
    asm volatile("cp.async.cg.shared.global [%0], [%1], 16;" :: "r"(s), "l"(g));
}
#define CP_COMMIT() asm volatile("cp.async.commit_group;" ::: "memory")
#define CP_WAIT1()  asm volatile("cp.async.wait_group 1;" ::: "memory")

__device__ __forceinline__ void ldm_x4(uint32_t* r, uint32_t addr) {
    asm volatile("ldmatrix.sync.aligned.m8n8.x4.shared.b16 {%0,%1,%2,%3}, [%4];"
                 : "=r"(r[0]), "=r"(r[1]), "=r"(r[2]), "=r"(r[3]) : "r"(addr));
}
__device__ __forceinline__ void ldm_x2(uint32_t* r, uint32_t addr) {
    asm volatile("ldmatrix.sync.aligned.m8n8.x2.shared.b16 {%0,%1}, [%2];"
                 : "=r"(r[0]), "=r"(r[1]) : "r"(addr));
}
__device__ __forceinline__ void mma_bf16(float* d, const uint32_t* a, const uint32_t* b) {
    asm volatile(
        "mma.sync.aligned.m16n8k16.row.col.f32.bf16.bf16.f32 "
        "{%0,%1,%2,%3}, {%4,%5,%6,%7}, {%8,%9}, {%0,%1,%2,%3};"
        : "+f"(d[0]), "+f"(d[1]), "+f"(d[2]), "+f"(d[3])
        : "r"(a[0]), "r"(a[1]), "r"(a[2]), "r"(a[3]), "r"(b[0]), "r"(b[1]));
}
__device__ __forceinline__ uint32_t pack_bf16(__nv_bfloat16 a, __nv_bfloat16 b) {
    __nv_bfloat162 t(a, b);
    return *(uint32_t*)&t;
}

// ---------------------------------------------------------------------------
// fp32 -> (bf16 hi, bf16 lo) split
// ---------------------------------------------------------------------------
__global__ __launch_bounds__(256)
void split_kernel(const float* __restrict__ s, __nv_bfloat16* __restrict__ h,
                  __nv_bfloat16* __restrict__ l, int n4)
{
    int i = blockIdx.x * blockDim.x + threadIdx.x;
    if (i >= n4) return;
    float4 v = ((const float4*)s)[i];
    __nv_bfloat16 h0 = __float2bfloat16(v.x);
    __nv_bfloat16 h1 = __float2bfloat16(v.y);
    __nv_bfloat16 h2 = __float2bfloat16(v.z);
    __nv_bfloat16 h3 = __float2bfloat16(v.w);
    __nv_bfloat16 l0 = __float2bfloat16(v.x - __bfloat162float(h0));
    __nv_bfloat16 l1 = __float2bfloat16(v.y - __bfloat162float(h1));
    __nv_bfloat16 l2 = __float2bfloat16(v.z - __bfloat162float(h2));
    __nv_bfloat16 l3 = __float2bfloat16(v.w - __bfloat162float(h3));
    ((__nv_bfloat162*)h)[i * 2]     = __nv_bfloat162(h0, h1);
    ((__nv_bfloat162*)h)[i * 2 + 1] = __nv_bfloat162(h2, h3);
    ((__nv_bfloat162*)l)[i * 2]     = __nv_bfloat162(l0, l1);
    ((__nv_bfloat162*)l)[i * 2 + 1] = __nv_bfloat162(l2, l3);
}

// ---------------------------------------------------------------------------
// bf16 3-term split GEMM via mma.sync: C[M,N] = A[M,K] * B[N,K]^T
// 128x128 CTA tile, BK=64, 2-stage cp.async double buffer, 8 warps (64x32).
// Per k-step: load all hi/lo fragments once, issue 3 split passes.
// MODE 0: fp32 store to C.
// MODE 1: Q,K -> bf16 hi/lo [b,h,s,hd]; V (n0>=2048) -> smem-staged
//         transpose, coalesced store to [b,h,hd,s].
// ---------------------------------------------------------------------------
template <int MODE>
__global__ __launch_bounds__(256)
void mma_gemm(const __nv_bfloat16* __restrict__ Ah, const __nv_bfloat16* __restrict__ Al,
              const __nv_bfloat16* __restrict__ Bh, const __nv_bfloat16* __restrict__ Bl,
              float* __restrict__ C, int N)
{
    extern __shared__ char smem[];
    const uint32_t sb = smem_u32(smem);
    const int tid  = threadIdx.x;
    const int warp = tid >> 5;
    const int lane = tid & 31;
    const int m0 = blockIdx.y * 128;
    const int n0 = blockIdx.x * 128;
    const int wm = (warp & 1) * 64;
    const int wn = (warp >> 1) * 32;

    const __nv_bfloat16* gsrc[4] = {
        Ah + (size_t)m0 * GK, Al + (size_t)m0 * GK,
        Bh + (size_t)n0 * GK, Bl + (size_t)n0 * GK };

    auto issue = [&](int chunk, int slot) {
        const int k0 = chunk * BK;
        const uint32_t st = sb + slot * STAGE_BYTES;
#pragma unroll
        for (int t = 0; t < 4; t++) {
            const __nv_bfloat16* g = gsrc[t] + k0;
            const uint32_t tb = st + t * TILE_BYTES;
#pragma unroll
            for (int i = 0; i < 4; i++) {
                const int idx = i * 256 + tid;    // 0..1023 16B chunks
                const int row = idx >> 3;
                const int c16 = idx & 7;
                cp_async16(tb + SWZ128(row * 128 + c16 * 16),
                           g + (size_t)row * GK + c16 * 8);
            }
        }
    };

    float acc[4][4][4];
#pragma unroll
    for (int a = 0; a < 4; a++)
#pragma unroll
        for (int b = 0; b < 4; b++)
#pragma unroll
            for (int c = 0; c < 4; c++) acc[a][b][c] = 0.f;

    issue(0, 0); CP_COMMIT();
    issue(1, 1); CP_COMMIT();

    for (int c = 0; c < NCHUNK; c++) {
        CP_WAIT1();
        __syncthreads();

        const uint32_t st = sb + (c & 1) * STAGE_BYTES;
        const uint32_t At_h = st;
        const uint32_t At_l = st + TILE_BYTES;
        const uint32_t Bt_h = st + 2 * TILE_BYTES;
        const uint32_t Bt_l = st + 3 * TILE_BYTES;

#pragma unroll
        for (int ks = 0; ks < 4; ks++) {
            uint32_t ah[4][4], al[4][4], bh[4][2], bl[4][2];
            const int ac16 = ks * 2 + (lane >> 4);
            const int bc16 = ks * 2 + ((lane >> 3) & 1);
#pragma unroll
            for (int mi = 0; mi < 4; mi++) {
                const int row = wm + mi * 16 + (lane & 15);
                const uint32_t off = SWZ128(row * 128 + ac16 * 16);
                ldm_x4(ah[mi], At_h + off);
                ldm_x4(al[mi], At_l + off);
            }
#pragma unroll
            for (int ni = 0; ni < 4; ni++) {
                const int row = wn + ni * 8 + (lane & 7);
                const uint32_t off = SWZ128(row * 128 + bc16 * 16);
                ldm_x2(bh[ni], Bt_h + off);
                ldm_x2(bl[ni], Bt_l + off);
            }
#pragma unroll
            for (int mi = 0; mi < 4; mi++)
#pragma unroll
                for (int ni = 0; ni < 4; ni++)
                    mma_bf16(acc[mi][ni], ah[mi], bh[ni]);
#pragma unroll
            for (int mi = 0; mi < 4; mi++)
#pragma unroll
                for (int ni = 0; ni < 4; ni++)
                    mma_bf16(acc[mi][ni], al[mi], bh[ni]);
#pragma unroll
            for (int mi = 0; mi < 4; mi++)
#pragma unroll
                for (int ni = 0; ni < 4; ni++)
                    mma_bf16(acc[mi][ni], ah[mi], bl[ni]);
        }
        __syncthreads();
        if (c + 2 < NCHUNK) issue(c + 2, c & 1);
        CP_COMMIT();
    }

    // ---- epilogue ----
    if (MODE == 1 && n0 >= 2 * DMODEL) {
        // V tile: stage transposed in smem, then coalesced store to [b,h,hd,s]
        __nv_bfloat16* vsh = (__nv_bfloat16*)smem;              // [128][VPITCH]
        __nv_bfloat16* vsl = vsh + 128 * VPITCH;
#pragma unroll
        for (int mi = 0; mi < 4; mi++) {
#pragma unroll
            for (int ni = 0; ni < 4; ni++) {
                const int nl = wn + ni * 8 + (lane & 3) * 2;
#pragma unroll
                for (int half = 0; half < 2; half++) {
                    const int ml = wm + mi * 16 + (lane >> 2) + half * 8;
                    const float v0 = acc[mi][ni][half * 2];
                    const float v1 = acc[mi][ni][half * 2 + 1];
                    const __nv_bfloat16 h0 = __float2bfloat16(v0);
                    const __nv_bfloat16 h1 = __float2bfloat16(v1);
                    vsh[nl * VPITCH + ml]       = h0;
                    vsh[(nl + 1) * VPITCH + ml] = h1;
                    vsl[nl * VPITCH + ml]       = __float2bfloat16(v0 - __bfloat162float(h0));
                    vsl[(nl + 1) * VPITCH + ml] = __float2bfloat16(v1 - __bfloat162float(h1));
                }
            }
        }
        __syncthreads();
        // flush: thread t -> row r = t>>1 (n_local), half hf = t&1 (64 bf16 = 128B)
        const int r  = tid >> 1;
        const int hf = tid & 1;
        const int n  = n0 + r;             // >= 2048
        const int dd = n - 2 * DMODEL;
        const int hh = dd >> 6;
        const int hc = dd & 63;
        const int b_ = m0 >> 11;
        const int s0_ = (m0 & 2047) + hf * 64;
        const size_t o = ((size_t)(b_ * NHEADS + hh) * HDIM + hc) * SEQ + s0_;
        const uint4* srch = (const uint4*)(vsh + r * VPITCH + hf * 64);
        const uint4* srcl = (const uint4*)(vsl + r * VPITCH + hf * 64);
        uint4* dsth = (uint4*)(g_vth + o);
        uint4* dstl = (uint4*)(g_vtl + o);
#pragma unroll
        for (int i = 0; i < 8; i++) { dsth[i] = srch[i]; dstl[i] = srcl[i]; }
    } else {
#pragma unroll
        for (int mi = 0; mi < 4; mi++) {
#pragma unroll
            for (int ni = 0; ni < 4; ni++) {
                const int mA = m0 + wm + mi * 16 + (lane >> 2);
                const int n  = n0 + wn + ni * 8 + (lane & 3) * 2;
#pragma unroll
                for (int half = 0; half < 2; half++) {
                    const int m = mA + half * 8;
                    const float v0 = acc[mi][ni][half * 2];
                    const float v1 = acc[mi][ni][half * 2 + 1];
                    if (MODE == 0) {
                        *(float2*)&C[(size_t)m * N + n] = make_float2(v0, v1);
                    } else {
                        const int b_ = m >> 11;
                        const int s_ = m & 2047;
                        const int which = n >> 10;     // 0=Q, 1=K here
                        const int dd = n & 1023;
                        const int hh = dd >> 6;
                        const int hc = dd & 63;
                        __nv_bfloat16 h0 = __float2bfloat16(v0);
                        __nv_bfloat16 h1 = __float2bfloat16(v1);
                        __nv_bfloat16 L0 = __float2bfloat16(v0 - __bfloat162float(h0));
                        __nv_bfloat16 L1 = __float2bfloat16(v1 - __bfloat162float(h1));
                        const size_t o = ((size_t)(b_ * NHEADS + hh) * SEQ + s_) * HDIM + hc;
                        __nv_bfloat16* dh = (which == 0) ? g_qh : g_kh;
                        __nv_bfloat16* dl = (which == 0) ? g_ql : g_kl;
                        *(__nv_bfloat162*)&dh[o] = __nv_bfloat162(h0, h1);
                        *(__nv_bfloat162*)&dl[o] = __nv_bfloat162(L0, L1);
                    }
                }
            }
        }
    }
}

// ---------------------------------------------------------------------------
// Causal flash attention via mma.sync, bf16 3-term split everywhere.
// CTA = 128 Q rows of one (b,h); 8 warps x 16 rows; K-tiles of 64, 2 stages.
// ---------------------------------------------------------------------------
__global__ __launch_bounds__(256)
void attn_mma(__nv_bfloat16* __restrict__ Oh, __nv_bfloat16* __restrict__ Ol)
{
    extern __shared__ char smem[];
    const uint32_t sb = smem_u32(smem);
    const int tid  = threadIdx.x;
    const int warp = tid >> 5;
    const int lane = tid & 31;
    const int qt = gridDim.x - 1 - blockIdx.x;   // big tiles first
    const int bh = blockIdx.y;
    const int b_ = bh >> 4;
    const int h  = bh & 15;
    const int q0 = qt * 128;
    const int ktmax = 2 * qt + 1;

    const size_t qkbase = (size_t)bh * SEQ * HDIM;
    const size_t vbase  = (size_t)bh * HDIM * SEQ;

    // ---- Q tiles (hi, lo): 128 x 64 bf16, 128B rows, swizzled ----
    {
        const __nv_bfloat16* src[2] = { g_qh + qkbase + (size_t)q0 * HDIM,
                                        g_ql + qkbase + (size_t)q0 * HDIM };
        const uint32_t dst[2] = { sb + AQH, sb + AQL };
#pragma unroll
        for (int t = 0; t < 2; t++)
#pragma unroll
            for (int i = 0; i < 4; i++) {
                const int idx = i * 256 + tid;      // 0..1023
                const int row = idx >> 3;
                const int c16 = idx & 7;
                cp_async16(dst[t] + SWZ128(row * 128 + c16 * 16),
                           src[t] + (size_t)row * HDIM + c16 * 8);
            }
        CP_COMMIT();
    }

    auto issue_kv = [&](int kt, int stg) {
        const uint32_t s0 = sb + ASTG + stg * ASTG_B;
        const __nv_bfloat16* ksrc[2] = { g_kh + qkbase + (size_t)kt * 64 * HDIM,
                                         g_kl + qkbase + (size_t)kt * 64 * HDIM };
#pragma unroll
        for (int t = 0; t < 2; t++)
#pragma unroll
            for (int i = 0; i < 2; i++) {
                const int idx = i * 256 + tid;      // 0..511
                const int row = idx >> 3;
                const int c16 = idx & 7;
                cp_async16(s0 + t * 8192 + SWZ128(row * 128 + c16 * 16),
                           ksrc[t] + (size_t)row * HDIM + c16 * 8);
            }
        const __nv_bfloat16* vsrc[2] = { g_vth + vbase + kt * 64,
                                         g_vtl + vbase + kt * 64 };
#pragma unroll
        for (int t = 0; t < 2; t++)
#pragma unroll
            for (int i = 0; i < 2; i++) {
                const int idx = i * 256 + tid;
                const int row = idx >> 3;           // hd row
                const int c16 = idx & 7;
                cp_async16(s0 + 16384 + t * 8192 + SWZ128(row * 128 + c16 * 16),
                           vsrc[t] + (size_t)row * SEQ + c16 * 8);
            }
    };

    issue_kv(0, 0); CP_COMMIT();
    CP_WAIT1();          // Q done (kv0 may be in flight)
    __syncthreads();

    // Q fragments, all 4 k-steps, hi & lo (Q is fixed for the whole CTA)
    uint32_t qfh[4][4], qfl[4][4];
    const int arow = warp * 16 + (lane & 15);
#pragma unroll
    for (int ks = 0; ks < 4; ks++) {
        const int c16 = ks * 2 + (lane >> 4);
        ldm_x4(qfh[ks], sb + AQH + SWZ128(arow * 128 + c16 * 16));
        ldm_x4(qfl[ks], sb + AQL + SWZ128(arow * 128 + c16 * 16));
    }

    float m_i[2] = {-1e30f, -1e30f}, l_i[2] = {0.f, 0.f};
    float o[8][4];
#pragma unroll
    for (int nt = 0; nt < 8; nt++)
#pragma unroll
        for (int c = 0; c < 4; c++) o[nt][c] = 0.f;

    const int r0 = lane >> 2;            // row within warp tile (and +8)
    const int cc = (lane & 3) * 2;       // col pair base

    for (int kt = 0; kt <= ktmax; kt++) {
        __syncthreads();                 // everyone done with buffer (kt+1)&1
        if (kt < ktmax) issue_kv(kt + 1, (kt + 1) & 1);
        CP_COMMIT();
        CP_WAIT1();
        __syncthreads();

        // per-warp fully-masked tile skip (barriers above/below still uniform)
        if (kt * 64 > q0 + warp * 16 + 15) continue;

        const uint32_t s0 = sb + ASTG + (kt & 1) * ASTG_B;

        // ---- S = Q K^T (3-term) ----
        float s[8][4];
#pragma unroll
        for (int nt = 0; nt < 8; nt++)
#pragma unroll
            for (int c = 0; c < 4; c++) s[nt][c] = 0.f;

#pragma unroll
        for (int ks = 0; ks < 4; ks++) {
            uint32_t bkh[8][2], bkl[8][2];
            const int c16 = ks * 2 + ((lane >> 3) & 1);
#pragma unroll
            for (int nt = 0; nt < 8; nt++) {
                const int row = nt * 8 + (lane & 7);
                ldm_x2(bkh[nt], s0 + SWZ128(row * 128 + c16 * 16));
                ldm_x2(bkl[nt], s0 + 8192 + SWZ128(row * 128 + c16 * 16));
            }
#pragma unroll
            for (int nt = 0; nt < 8; nt++) {
                mma_bf16(s[nt], qfh[ks], bkh[nt]);
                mma_bf16(s[nt], qfl[ks], bkh[nt]);
                mma_bf16(s[nt], qfh[ks], bkl[nt]);
            }
        }

        // ---- scale + causal mask ----
        const bool needmask = (kt * 64 + 63 > q0 + warp * 16);
#pragma unroll
        for (int nt = 0; nt < 8; nt++)
#pragma unroll
            for (int c = 0; c < 4; c++) {
                float v = s[nt][c] * 0.125f;
                if (needmask) {
                    const int gq = q0 + warp * 16 + r0 + ((c >> 1) ? 8 : 0);
                    const int gk = kt * 64 + nt * 8 + cc + (c & 1);
                    if (gk > gq) v = -1e30f;
                }
                s[nt][c] = v;
            }

        // ---- online softmax (2 rows per thread) ----
#pragma unroll
        for (int hf = 0; hf < 2; hf++) {
            float mx = -1e30f;
#pragma unroll
            for (int nt = 0; nt < 8; nt++)
                mx = fmaxf(mx, fmaxf(s[nt][hf * 2], s[nt][hf * 2 + 1]));
            mx = fmaxf(mx, __shfl_xor_sync(0xffffffffu, mx, 1));
            mx = fmaxf(mx, __shfl_xor_sync(0xffffffffu, mx, 2));
            const float mnew = fmaxf(m_i[hf], mx);
            const float alpha = __expf(m_i[hf] - mnew);
            float rs = 0.f;
#pragma unroll
            for (int nt = 0; nt < 8; nt++) {
                const float p0 = __expf(s[nt][hf * 2]     - mnew);
                const float p1 = __expf(s[nt][hf * 2 + 1] - mnew);
                s[nt][hf * 2] = p0; s[nt][hf * 2 + 1] = p1;
                rs += p0 + p1;
            }
            rs += __shfl_xor_sync(0xffffffffu, rs, 1);
            rs += __shfl_xor_sync(0xffffffffu, rs, 2);
            l_i[hf] = l_i[hf] * alpha + rs;
            m_i[hf] = mnew;
#pragma unroll
            for (int nt = 0; nt < 8; nt++) {
                o[nt][hf * 2] *= alpha; o[nt][hf * 2 + 1] *= alpha;
            }
        }

        // ---- O += P V (P hi/lo in regs; V^T tiles) ----
#pragma unroll
        for (int j = 0; j < 4; j++) {
            uint32_t ah[4], al[4];
#pragma unroll
            for (int half = 0; half < 2; half++) {
                const float p0 = s[2 * j + half][0], p1 = s[2 * j + half][1];
                const float p2 = s[2 * j + half][2], p3 = s[2 * j + half][3];
                const __nv_bfloat16 h0 = __float2bfloat16(p0), h1 = __float2bfloat16(p1);
                const __nv_bfloat16 h2 = __float2bfloat16(p2), h3 = __float2bfloat16(p3);
                ah[half * 2]     = pack_bf16(h0, h1);
                ah[half * 2 + 1] = pack_bf16(h2, h3);
                al[half * 2]     = pack_bf16(__float2bfloat16(p0 - __bfloat162float(h0)),
                                             __float2bfloat16(p1 - __bfloat162float(h1)));
                al[half * 2 + 1] = pack_bf16(__float2bfloat16(p2 - __bfloat162float(h2)),
                                             __float2bfloat16(p3 - __bfloat162float(h3)));
            }
            const int c16 = j * 2 + ((lane >> 3) & 1);
#pragma unroll
            for (int nt = 0; nt < 8; nt++) {
                const int row = nt * 8 + (lane & 7);
                uint32_t vh[2], vl[2];
                ldm_x2(vh, s0 + 16384 + SWZ128(row * 128 + c16 * 16));
                ldm_x2(vl, s0 + 24576 + SWZ128(row * 128 + c16 * 16));
                mma_bf16(o[nt], ah, vh);
                mma_bf16(o[nt], al, vh);
                mma_bf16(o[nt], ah, vl);
            }
        }
    }

    // ---- epilogue: bf16 hi/lo into [b,s,D] ----
#pragma unroll
    for (int hf = 0; hf < 2; hf++) {
        const float inv = 1.f / l_i[hf];
        const int gq = q0 + warp * 16 + r0 + hf * 8;
        const size_t off = ((size_t)b_ * SEQ + gq) * DMODEL + h * HDIM + cc;
#pragma unroll
        for (int nt = 0; nt < 8; nt++) {
            const float v0 = o[nt][hf * 2] * inv;
            const float v1 = o[nt][hf * 2 + 1] * inv;
            const __nv_bfloat16 h0 = __float2bfloat16(v0);
            const __nv_bfloat16 h1 = __float2bfloat16(v1);
            *(__nv_bfloat162*)&Oh[off + nt * 8] = __nv_bfloat162(h0, h1);
            *(__nv_bfloat162*)&Ol[off + nt * 8] =
                __nv_bfloat162(__float2bfloat16(v0 - __bfloat162float(h0)),
                               __float2bfloat16(v1 - __bfloat162float(h1)));
        }
    }
}

// ---------------------------------------------------------------------------
// Launch
// ---------------------------------------------------------------------------
extern "C" void kernel_launch(void* const* d_in, const int* in_sizes, int n_in,
                              void* d_out, int out_size)
{
    const float* x     = (const float*)d_in[0];
    const float* w_qkv = (const float*)d_in[1];
    const float* w_out = (const float*)d_in[2];
    float* out = (float*)d_out;

    __nv_bfloat16 *pxh, *pxl, *pwqh, *pwql, *pwoh, *pwol, *poh, *pol;
    cudaGetSymbolAddress((void**)&pxh, g_xh);
    cudaGetSymbolAddress((void**)&pxl, g_xl);
    cudaGetSymbolAddress((void**)&pwqh, g_wqh);
    cudaGetSymbolAddress((void**)&pwql, g_wql);
    cudaGetSymbolAddress((void**)&pwoh, g_woh);
    cudaGetSymbolAddress((void**)&pwol, g_wol);
    cudaGetSymbolAddress((void**)&poh, g_oh);
    cudaGetSymbolAddress((void**)&pol, g_ol);

    cudaFuncSetAttribute(mma_gemm<0>, cudaFuncAttributeMaxDynamicSharedMemorySize, GEMM_SMEM);
    cudaFuncSetAttribute(mma_gemm<1>, cudaFuncAttributeMaxDynamicSharedMemorySize, GEMM_SMEM);
    cudaFuncSetAttribute(attn_mma,    cudaFuncAttributeMaxDynamicSharedMemorySize, ATT_SMEM);

    // 1) bf16 hi/lo splits
    split_kernel<<<(MROWS * DMODEL / 4 + 255) / 256, 256>>>(x, pxh, pxl, MROWS * DMODEL / 4);
    split_kernel<<<(QKV_N * DMODEL / 4 + 255) / 256, 256>>>(w_qkv, pwqh, pwql, QKV_N * DMODEL / 4);
    split_kernel<<<(DMODEL * DMODEL / 4 + 255) / 256, 256>>>(w_out, pwoh, pwol, DMODEL * DMODEL / 4);

    // 2) QKV projection -> bf16 hi/lo Q,K,V^T in head layout
    {
        dim3 grid(QKV_N / 128, MROWS / 128);
        mma_gemm<1><<<grid, 256, GEMM_SMEM>>>(pxh, pxl, pwqh, pwql, nullptr, QKV_N);
    }
    // 3) causal flash attention (tensor cores)
    {
        dim3 grid(SEQ / 128, BATCH * NHEADS);
        attn_mma<<<grid, 256, ATT_SMEM>>>(poh, pol);
    }
    // 4) out projection
    {
        dim3 grid(DMODEL / 128, MROWS / 128);
        mma_gemm<0><<<grid, 256, GEMM_SMEM>>>(poh, pol, pwoh, pwol, out, DMODEL);
    }
}

// round 9
// speedup vs baseline: 3.5353x; 1.0238x over previous
#include <cuda_runtime.h>
#include <cuda_bf16.h>
#include <cstdint>

// ---------------------------------------------------------------------------
// Problem constants
// ---------------------------------------------------------------------------
#define BATCH 4
#define SEQ 2048
#define DMODEL 1024
#define NHEADS 16
#define HDIM 64
#define MROWS (BATCH * SEQ)        // 8192
#define QKV_N (3 * DMODEL)         // 3072
#define GK DMODEL                  // K of both GEMMs = 1024

// GEMM tiling: CTA 128(M) x 256(N), BK=64, warp tile 64x64, 8 warps
#define GBM 128
#define GBN 256
#define BK 64
#define NCHUNK (GK / BK)           // 16
#define A_TILE_B 16384             // 128 x 64 bf16
#define B_TILE_B 32768             // 256 x 64 bf16
#define STAGE_BYTES (2 * A_TILE_B + 2 * B_TILE_B)   // 96KB
#define GEMM_SMEM (2 * STAGE_BYTES)                 // 196608

// Attention smem map (dynamic): Qh 16K, Ql 16K, then 2 stages x 32K
#define AQH 0
#define AQL 16384
#define ASTG 32768
#define ASTG_B 32768               // per stage: KH 0, KL 8K, VH 16K, VL 24K
#define ATT_SMEM (ASTG + 2 * ASTG_B)   // 98304

// V-transpose staging pitch (elements)
#define VPITCH 136

// ---------------------------------------------------------------------------
// Scratch (__device__ globals; no allocs allowed)
// ---------------------------------------------------------------------------
#define QKV_ELEMS (BATCH * NHEADS * SEQ * HDIM)
__device__ __align__(128) __nv_bfloat16 g_qh[QKV_ELEMS], g_ql[QKV_ELEMS];   // [b,h,s,hd]
__device__ __align__(128) __nv_bfloat16 g_kh[QKV_ELEMS], g_kl[QKV_ELEMS];   // [b,h,s,hd]
__device__ __align__(128) __nv_bfloat16 g_vth[QKV_ELEMS], g_vtl[QKV_ELEMS]; // [b,h,hd,s]

__device__ __align__(128) __nv_bfloat16 g_xh[MROWS * DMODEL],  g_xl[MROWS * DMODEL];
__device__ __align__(128) __nv_bfloat16 g_wqh[QKV_N * DMODEL], g_wql[QKV_N * DMODEL];
__device__ __align__(128) __nv_bfloat16 g_woh[DMODEL * DMODEL], g_wol[DMODEL * DMODEL];
__device__ __align__(128) __nv_bfloat16 g_oh[MROWS * DMODEL],  g_ol[MROWS * DMODEL];

// ---------------------------------------------------------------------------
// Helpers
// ---------------------------------------------------------------------------
__device__ __forceinline__ uint32_t smem_u32(const void* p) {
    uint32_t a;
    asm("{ .reg .u64 t; cvta.to.shared.u64 t, %1; cvt.u32.u64 %0, t; }"
        : "=r"(a) : "l"(p));
    return a;
}

#define SWZ128(o) ((o) ^ (((o) >> 3) & 0x70))

__device__ __forceinline__ void cp_async16(uint32_t s, const void* g) {
    asm volatile("cp.async.cg.shared.global [%0], [%1], 16;" :: "r"(s), "l"(g));
}
#define CP_COMMIT() asm volatile("cp.async.commit_group;" ::: "memory")
#define CP_WAIT1()  asm volatile("cp.async.wait_group 1;" ::: "memory")

__device__ __forceinline__ void ldm_x4(uint32_t* r, uint32_t addr) {
    asm volatile("ldmatrix.sync.aligned.m8n8.x4.shared.b16 {%0,%1,%2,%3}, [%4];"
                 : "=r"(r[0]), "=r"(r[1]), "=r"(r[2]), "=r"(r[3]) : "r"(addr));
}
__device__ __forceinline__ void mma_bf16(float* d, const uint32_t* a, const uint32_t* b) {
    asm volatile(
        "mma.sync.aligned.m16n8k16.row.col.f32.bf16.bf16.f32 "
        "{%0,%1,%2,%3}, {%4,%5,%6,%7}, {%8,%9}, {%0,%1,%2,%3};"
        : "+f"(d[0]), "+f"(d[1]), "+f"(d[2]), "+f"(d[3])
        : "r"(a[0]), "r"(a[1]), "r"(a[2]), "r"(a[3]), "r"(b[0]), "r"(b[1]));
}
__device__ __forceinline__ uint32_t pack_bf16(__nv_bfloat16 a, __nv_bfloat16 b) {
    __nv_bfloat162 t(a, b);
    return *(uint32_t*)&t;
}

// ---------------------------------------------------------------------------
// fp32 -> (bf16 hi, bf16 lo) split
// ---------------------------------------------------------------------------
__global__ __launch_bounds__(256)
void split_kernel(const float* __restrict__ s, __nv_bfloat16* __restrict__ h,
                  __nv_bfloat16* __restrict__ l, int n4)
{
    int i = blockIdx.x * blockDim.x + threadIdx.x;
    if (i >= n4) return;
    float4 v = ((const float4*)s)[i];
    __nv_bfloat16 h0 = __float2bfloat16(v.x);
    __nv_bfloat16 h1 = __float2bfloat16(v.y);
    __nv_bfloat16 h2 = __float2bfloat16(v.z);
    __nv_bfloat16 h3 = __float2bfloat16(v.w);
    __nv_bfloat16 l0 = __float2bfloat16(v.x - __bfloat162float(h0));
    __nv_bfloat16 l1 = __float2bfloat16(v.y - __bfloat162float(h1));
    __nv_bfloat16 l2 = __float2bfloat16(v.z - __bfloat162float(h2));
    __nv_bfloat16 l3 = __float2bfloat16(v.w - __bfloat162float(h3));
    ((__nv_bfloat162*)h)[i * 2]     = __nv_bfloat162(h0, h1);
    ((__nv_bfloat162*)h)[i * 2 + 1] = __nv_bfloat162(h2, h3);
    ((__nv_bfloat162*)l)[i * 2]     = __nv_bfloat162(l0, l1);
    ((__nv_bfloat162*)l)[i * 2 + 1] = __nv_bfloat162(l2, l3);
}

// ---------------------------------------------------------------------------
// bf16 3-term split GEMM via mma.sync: C[M,N] = A[M,K] * B[N,K]^T
// CTA 128x256, BK=64, 2-stage cp.async double buffer, 8 warps (64x64 each).
// MODE 0: fp32 store to C.
// MODE 1: Q,K -> bf16 hi/lo [b,h,s,hd]; V (n0>=2048) -> smem-staged
//         transpose, coalesced store to [b,h,hd,s].
// ---------------------------------------------------------------------------
template <int MODE>
__global__ __launch_bounds__(256, 1)
void mma_gemm(const __nv_bfloat16* __restrict__ Ah, const __nv_bfloat16* __restrict__ Al,
              const __nv_bfloat16* __restrict__ Bh, const __nv_bfloat16* __restrict__ Bl,
              float* __restrict__ C, int N)
{
    extern __shared__ char smem[];
    const uint32_t sb = smem_u32(smem);
    const int tid  = threadIdx.x;
    const int warp = tid >> 5;
    const int lane = tid & 31;
    const int m0 = blockIdx.y * GBM;
    const int n0 = blockIdx.x * GBN;
    const int wm = (warp & 1) * 64;       // 2 x 4 warp grid, 64x64 tiles
    const int wn = (warp >> 1) * 64;

    const __nv_bfloat16* gA[2] = { Ah + (size_t)m0 * GK, Al + (size_t)m0 * GK };
    const __nv_bfloat16* gB[2] = { Bh + (size_t)n0 * GK, Bl + (size_t)n0 * GK };

    auto issue = [&](int chunk, int slot) {
        const int k0 = chunk * BK;
        const uint32_t st = sb + slot * STAGE_BYTES;
#pragma unroll
        for (int t = 0; t < 2; t++) {
            const __nv_bfloat16* g = gA[t] + k0;
            const uint32_t tb = st + t * A_TILE_B;
#pragma unroll
            for (int i = 0; i < 4; i++) {
                const int idx = i * 256 + tid;     // 0..1023
                const int row = idx >> 3;
                const int c16 = idx & 7;
                cp_async16(tb + SWZ128(row * 128 + c16 * 16),
                           g + (size_t)row * GK + c16 * 8);
            }
        }
#pragma unroll
        for (int t = 0; t < 2; t++) {
            const __nv_bfloat16* g = gB[t] + k0;
            const uint32_t tb = st + 2 * A_TILE_B + t * B_TILE_B;
#pragma unroll
            for (int i = 0; i < 8; i++) {
                const int idx = i * 256 + tid;     // 0..2047
                const int row = idx >> 3;
                const int c16 = idx & 7;
                cp_async16(tb + SWZ128(row * 128 + c16 * 16),
                           g + (size_t)row * GK + c16 * 8);
            }
        }
    };

    float acc[4][8][4];
#pragma unroll
    for (int a = 0; a < 4; a++)
#pragma unroll
        for (int b = 0; b < 8; b++)
#pragma unroll
            for (int c = 0; c < 4; c++) acc[a][b][c] = 0.f;

    issue(0, 0); CP_COMMIT();
    issue(1, 1); CP_COMMIT();

    const int brow = ((lane >> 4) << 3) + (lane & 7);   // x4 B-pair row within 16

    for (int c = 0; c < NCHUNK; c++) {
        CP_WAIT1();
        __syncthreads();

        const uint32_t st = sb + (c & 1) * STAGE_BYTES;
        const uint32_t At_h = st;
        const uint32_t At_l = st + A_TILE_B;
        const uint32_t Bt_h = st + 2 * A_TILE_B;
        const uint32_t Bt_l = Bt_h + B_TILE_B;

#pragma unroll
        for (int ks = 0; ks < 4; ks++) {
            uint32_t ah[4][4], al[4][4];
            const int ac16 = ks * 2 + (lane >> 4);
            const int bc16 = ks * 2 + ((lane >> 3) & 1);
#pragma unroll
            for (int mi = 0; mi < 4; mi++) {
                const int row = wm + mi * 16 + (lane & 15);
                const uint32_t off = SWZ128(row * 128 + ac16 * 16);
                ldm_x4(ah[mi], At_h + off);
                ldm_x4(al[mi], At_l + off);
            }
#pragma unroll
            for (int np = 0; np < 4; np++) {
                uint32_t b4h[4], b4l[4];
                const int row = wn + np * 16 + brow;
                const uint32_t off = SWZ128(row * 128 + bc16 * 16);
                ldm_x4(b4h, Bt_h + off);
                ldm_x4(b4l, Bt_l + off);
#pragma unroll
                for (int mi = 0; mi < 4; mi++) {
                    mma_bf16(acc[mi][np * 2],     ah[mi], b4h);
                    mma_bf16(acc[mi][np * 2 + 1], ah[mi], b4h + 2);
                }
#pragma unroll
                for (int mi = 0; mi < 4; mi++) {
                    mma_bf16(acc[mi][np * 2],     al[mi], b4h);
                    mma_bf16(acc[mi][np * 2 + 1], al[mi], b4h + 2);
                }
#pragma unroll
                for (int mi = 0; mi < 4; mi++) {
                    mma_bf16(acc[mi][np * 2],     ah[mi], b4l);
                    mma_bf16(acc[mi][np * 2 + 1], ah[mi], b4l + 2);
                }
            }
        }
        __syncthreads();
        if (c + 2 < NCHUNK) issue(c + 2, c & 1);
        CP_COMMIT();
    }

    // ---- epilogue ----
    if (MODE == 1 && n0 >= 2 * DMODEL) {
        // V tile: stage transposed in smem, then coalesced store to [b,h,hd,s]
        __nv_bfloat16* vsh = (__nv_bfloat16*)smem;              // [256][VPITCH]
        __nv_bfloat16* vsl = vsh + 256 * VPITCH;
#pragma unroll
        for (int mi = 0; mi < 4; mi++) {
#pragma unroll
            for (int ni = 0; ni < 8; ni++) {
                const int nl = wn + ni * 8 + (lane & 3) * 2;
#pragma unroll
                for (int half = 0; half < 2; half++) {
                    const int ml = wm + mi * 16 + (lane >> 2) + half * 8;
                    const float v0 = acc[mi][ni][half * 2];
                    const float v1 = acc[mi][ni][half * 2 + 1];
                    const __nv_bfloat16 h0 = __float2bfloat16(v0);
                    const __nv_bfloat16 h1 = __float2bfloat16(v1);
                    vsh[nl * VPITCH + ml]       = h0;
                    vsh[(nl + 1) * VPITCH + ml] = h1;
                    vsl[nl * VPITCH + ml]       = __float2bfloat16(v0 - __bfloat162float(h0));
                    vsl[(nl + 1) * VPITCH + ml] = __float2bfloat16(v1 - __bfloat162float(h1));
                }
            }
        }
        __syncthreads();
        // flush: thread t -> n-row r = tid, 128 contiguous m-elems (256B) hi+lo
        const int r = tid;
        const int dd = n0 + r - 2 * DMODEL;
        const int hh = dd >> 6;
        const int hc = dd & 63;
        const int b_ = m0 >> 11;
        const int s0_ = m0 & 2047;
        const size_t o = ((size_t)(b_ * NHEADS + hh) * HDIM + hc) * SEQ + s0_;
        const uint4* srch = (const uint4*)(vsh + r * VPITCH);
        const uint4* srcl = (const uint4*)(vsl + r * VPITCH);
        uint4* dsth = (uint4*)(g_vth + o);
        uint4* dstl = (uint4*)(g_vtl + o);
#pragma unroll
        for (int i = 0; i < 16; i++) { dsth[i] = srch[i]; dstl[i] = srcl[i]; }
    } else {
#pragma unroll
        for (int mi = 0; mi < 4; mi++) {
#pragma unroll
            for (int ni = 0; ni < 8; ni++) {
                const int mA = m0 + wm + mi * 16 + (lane >> 2);
                const int n  = n0 + wn + ni * 8 + (lane & 3) * 2;
#pragma unroll
                for (int half = 0; half < 2; half++) {
                    const int m = mA + half * 8;
                    const float v0 = acc[mi][ni][half * 2];
                    const float v1 = acc[mi][ni][half * 2 + 1];
                    if (MODE == 0) {
                        *(float2*)&C[(size_t)m * N + n] = make_float2(v0, v1);
                    } else {
                        const int b_ = m >> 11;
                        const int s_ = m & 2047;
                        const int which = n >> 10;     // 0=Q, 1=K here
                        const int dd = n & 1023;
                        const int hh = dd >> 6;
                        const int hc = dd & 63;
                        __nv_bfloat16 h0 = __float2bfloat16(v0);
                        __nv_bfloat16 h1 = __float2bfloat16(v1);
                        __nv_bfloat16 L0 = __float2bfloat16(v0 - __bfloat162float(h0));
                        __nv_bfloat16 L1 = __float2bfloat16(v1 - __bfloat162float(h1));
                        const size_t o = ((size_t)(b_ * NHEADS + hh) * SEQ + s_) * HDIM + hc;
                        __nv_bfloat16* dh = (which == 0) ? g_qh : g_kh;
                        __nv_bfloat16* dl = (which == 0) ? g_ql : g_kl;
                        *(__nv_bfloat162*)&dh[o] = __nv_bfloat162(h0, h1);
                        *(__nv_bfloat162*)&dl[o] = __nv_bfloat162(L0, L1);
                    }
                }
            }
        }
    }
}

// ---------------------------------------------------------------------------
// Causal flash attention via mma.sync, bf16 3-term split everywhere.
// CTA = 128 Q rows of one (b,h); 8 warps x 16 rows; K-tiles of 64, 2 stages.
// ---------------------------------------------------------------------------
__global__ __launch_bounds__(256)
void attn_mma(__nv_bfloat16* __restrict__ Oh, __nv_bfloat16* __restrict__ Ol)
{
    extern __shared__ char smem[];
    const uint32_t sb = smem_u32(smem);
    const int tid  = threadIdx.x;
    const int warp = tid >> 5;
    const int lane = tid & 31;
    const int qt = gridDim.x - 1 - blockIdx.x;   // big tiles first
    const int bh = blockIdx.y;
    const int b_ = bh >> 4;
    const int h  = bh & 15;
    const int q0 = qt * 128;
    const int ktmax = 2 * qt + 1;

    const size_t qkbase = (size_t)bh * SEQ * HDIM;
    const size_t vbase  = (size_t)bh * HDIM * SEQ;

    // ---- Q tiles (hi, lo): 128 x 64 bf16, 128B rows, swizzled ----
    {
        const __nv_bfloat16* src[2] = { g_qh + qkbase + (size_t)q0 * HDIM,
                                        g_ql + qkbase + (size_t)q0 * HDIM };
        const uint32_t dst[2] = { sb + AQH, sb + AQL };
#pragma unroll
        for (int t = 0; t < 2; t++)
#pragma unroll
            for (int i = 0; i < 4; i++) {
                const int idx = i * 256 + tid;      // 0..1023
                const int row = idx >> 3;
                const int c16 = idx & 7;
                cp_async16(dst[t] + SWZ128(row * 128 + c16 * 16),
                           src[t] + (size_t)row * HDIM + c16 * 8);
            }
        CP_COMMIT();
    }

    auto issue_kv = [&](int kt, int stg) {
        const uint32_t s0 = sb + ASTG + stg * ASTG_B;
        const __nv_bfloat16* ksrc[2] = { g_kh + qkbase + (size_t)kt * 64 * HDIM,
                                         g_kl + qkbase + (size_t)kt * 64 * HDIM };
#pragma unroll
        for (int t = 0; t < 2; t++)
#pragma unroll
            for (int i = 0; i < 2; i++) {
                const int idx = i * 256 + tid;      // 0..511
                const int row = idx >> 3;
                const int c16 = idx & 7;
                cp_async16(s0 + t * 8192 + SWZ128(row * 128 + c16 * 16),
                           ksrc[t] + (size_t)row * HDIM + c16 * 8);
            }
        const __nv_bfloat16* vsrc[2] = { g_vth + vbase + kt * 64,
                                         g_vtl + vbase + kt * 64 };
#pragma unroll
        for (int t = 0; t < 2; t++)
#pragma unroll
            for (int i = 0; i < 2; i++) {
                const int idx = i * 256 + tid;
                const int row = idx >> 3;           // hd row
                const int c16 = idx & 7;
                cp_async16(s0 + 16384 + t * 8192 + SWZ128(row * 128 + c16 * 16),
                           vsrc[t] + (size_t)row * SEQ + c16 * 8);
            }
    };

    issue_kv(0, 0); CP_COMMIT();
    CP_WAIT1();          // Q done (kv0 may be in flight)
    __syncthreads();

    // Q fragments, all 4 k-steps, hi & lo (Q is fixed for the whole CTA)
    uint32_t qfh[4][4], qfl[4][4];
    const int arow = warp * 16 + (lane & 15);
#pragma unroll
    for (int ks = 0; ks < 4; ks++) {
        const int c16 = ks * 2 + (lane >> 4);
        ldm_x4(qfh[ks], sb + AQH + SWZ128(arow * 128 + c16 * 16));
        ldm_x4(qfl[ks], sb + AQL + SWZ128(arow * 128 + c16 * 16));
    }

    float m_i[2] = {-1e30f, -1e30f}, l_i[2] = {0.f, 0.f};
    float o[8][4];
#pragma unroll
    for (int nt = 0; nt < 8; nt++)
#pragma unroll
        for (int c = 0; c < 4; c++) o[nt][c] = 0.f;

    const int r0 = lane >> 2;            // row within warp tile (and +8)
    const int cc = (lane & 3) * 2;       // col pair base
    const int brow = ((lane >> 4) << 3) + (lane & 7);   // x4 pair row within 16

    for (int kt = 0; kt <= ktmax; kt++) {
        __syncthreads();                 // everyone done with buffer (kt+1)&1
        if (kt < ktmax) issue_kv(kt + 1, (kt + 1) & 1);
        CP_COMMIT();
        CP_WAIT1();
        __syncthreads();

        // per-warp fully-masked tile skip (barriers above/below still uniform)
        if (kt * 64 > q0 + warp * 16 + 15) continue;

        const uint32_t s0 = sb + ASTG + (kt & 1) * ASTG_B;

        // ---- S = Q K^T (3-term) ----
        float s[8][4];
#pragma unroll
        for (int nt = 0; nt < 8; nt++)
#pragma unroll
            for (int c = 0; c < 4; c++) s[nt][c] = 0.f;

#pragma unroll
        for (int ks = 0; ks < 4; ks++) {
            const int c16 = ks * 2 + ((lane >> 3) & 1);
#pragma unroll
            for (int np = 0; np < 4; np++) {
                uint32_t b4h[4], b4l[4];
                const int row = np * 16 + brow;
                const uint32_t off = SWZ128(row * 128 + c16 * 16);
                ldm_x4(b4h, s0 + off);
                ldm_x4(b4l, s0 + 8192 + off);
                mma_bf16(s[np * 2],     qfh[ks], b4h);
                mma_bf16(s[np * 2 + 1], qfh[ks], b4h + 2);
                mma_bf16(s[np * 2],     qfl[ks], b4h);
                mma_bf16(s[np * 2 + 1], qfl[ks], b4h + 2);
                mma_bf16(s[np * 2],     qfh[ks], b4l);
                mma_bf16(s[np * 2 + 1], qfh[ks], b4l + 2);
            }
        }

        // ---- scale + causal mask ----
        const bool needmask = (kt * 64 + 63 > q0 + warp * 16);
#pragma unroll
        for (int nt = 0; nt < 8; nt++)
#pragma unroll
            for (int c = 0; c < 4; c++) {
                float v = s[nt][c] * 0.125f;
                if (needmask) {
                    const int gq = q0 + warp * 16 + r0 + ((c >> 1) ? 8 : 0);
                    const int gk = kt * 64 + nt * 8 + cc + (c & 1);
                    if (gk > gq) v = -1e30f;
                }
                s[nt][c] = v;
            }

        // ---- online softmax (2 rows per thread) ----
#pragma unroll
        for (int hf = 0; hf < 2; hf++) {
            float mx = -1e30f;
#pragma unroll
            for (int nt = 0; nt < 8; nt++)
                mx = fmaxf(mx, fmaxf(s[nt][hf * 2], s[nt][hf * 2 + 1]));
            mx = fmaxf(mx, __shfl_xor_sync(0xffffffffu, mx, 1));
            mx = fmaxf(mx, __shfl_xor_sync(0xffffffffu, mx, 2));
            const float mnew = fmaxf(m_i[hf], mx);
            const float alpha = __expf(m_i[hf] - mnew);
            float rs = 0.f;
#pragma unroll
            for (int nt = 0; nt < 8; nt++) {
                const float p0 = __expf(s[nt][hf * 2]     - mnew);
                const float p1 = __expf(s[nt][hf * 2 + 1] - mnew);
                s[nt][hf * 2] = p0; s[nt][hf * 2 + 1] = p1;
                rs += p0 + p1;
            }
            rs += __shfl_xor_sync(0xffffffffu, rs, 1);
            rs += __shfl_xor_sync(0xffffffffu, rs, 2);
            l_i[hf] = l_i[hf] * alpha + rs;
            m_i[hf] = mnew;
#pragma unroll
            for (int nt = 0; nt < 8; nt++) {
                o[nt][hf * 2] *= alpha; o[nt][hf * 2 + 1] *= alpha;
            }
        }

        // ---- O += P V (P hi/lo in regs; V^T tiles) ----
#pragma unroll
        for (int j = 0; j < 4; j++) {
            uint32_t ah[4], al[4];
#pragma unroll
            for (int half = 0; half < 2; half++) {
                const float p0 = s[2 * j + half][0], p1 = s[2 * j + half][1];
                const float p2 = s[2 * j + half][2], p3 = s[2 * j + half][3];
                const __nv_bfloat16 h0 = __float2bfloat16(p0), h1 = __float2bfloat16(p1);
                const __nv_bfloat16 h2 = __float2bfloat16(p2), h3 = __float2bfloat16(p3);
                ah[half * 2]     = pack_bf16(h0, h1);
                ah[half * 2 + 1] = pack_bf16(h2, h3);
                al[half * 2]     = pack_bf16(__float2bfloat16(p0 - __bfloat162float(h0)),
                                             __float2bfloat16(p1 - __bfloat162float(h1)));
                al[half * 2 + 1] = pack_bf16(__float2bfloat16(p2 - __bfloat162float(h2)),
                                             __float2bfloat16(p3 - __bfloat162float(h3)));
            }
            const int c16 = j * 2 + ((lane >> 3) & 1);
#pragma unroll
            for (int np = 0; np < 4; np++) {
                const int row = np * 16 + brow;
                const uint32_t off = SWZ128(row * 128 + c16 * 16);
                uint32_t v4h[4], v4l[4];
                ldm_x4(v4h, s0 + 16384 + off);
                ldm_x4(v4l, s0 + 24576 + off);
                mma_bf16(o[np * 2],     ah, v4h);
                mma_bf16(o[np * 2 + 1], ah, v4h + 2);
                mma_bf16(o[np * 2],     al, v4h);
                mma_bf16(o[np * 2 + 1], al, v4h + 2);
                mma_bf16(o[np * 2],     ah, v4l);
                mma_bf16(o[np * 2 + 1], ah, v4l + 2);
            }
        }
    }

    // ---- epilogue: bf16 hi/lo into [b,s,D] ----
#pragma unroll
    for (int hf = 0; hf < 2; hf++) {
        const float inv = 1.f / l_i[hf];
        const int gq = q0 + warp * 16 + r0 + hf * 8;
        const size_t off = ((size_t)b_ * SEQ + gq) * DMODEL + h * HDIM + cc;
#pragma unroll
        for (int nt = 0; nt < 8; nt++) {
            const float v0 = o[nt][hf * 2] * inv;
            const float v1 = o[nt][hf * 2 + 1] * inv;
            const __nv_bfloat16 h0 = __float2bfloat16(v0);
            const __nv_bfloat16 h1 = __float2bfloat16(v1);
            *(__nv_bfloat162*)&Oh[off + nt * 8] = __nv_bfloat162(h0, h1);
            *(__nv_bfloat162*)&Ol[off + nt * 8] =
                __nv_bfloat162(__float2bfloat16(v0 - __bfloat162float(h0)),
                               __float2bfloat16(v1 - __bfloat162float(h1)));
        }
    }
}

// ---------------------------------------------------------------------------
// Launch
// ---------------------------------------------------------------------------
extern "C" void kernel_launch(void* const* d_in, const int* in_sizes, int n_in,
                              void* d_out, int out_size)
{
    const float* x     = (const float*)d_in[0];
    const float* w_qkv = (const float*)d_in[1];
    const float* w_out = (const float*)d_in[2];
    float* out = (float*)d_out;

    __nv_bfloat16 *pxh, *pxl, *pwqh, *pwql, *pwoh, *pwol, *poh, *pol;
    cudaGetSymbolAddress((void**)&pxh, g_xh);
    cudaGetSymbolAddress((void**)&pxl, g_xl);
    cudaGetSymbolAddress((void**)&pwqh, g_wqh);
    cudaGetSymbolAddress((void**)&pwql, g_wql);
    cudaGetSymbolAddress((void**)&pwoh, g_woh);
    cudaGetSymbolAddress((void**)&pwol, g_wol);
    cudaGetSymbolAddress((void**)&poh, g_oh);
    cudaGetSymbolAddress((void**)&pol, g_ol);

    cudaFuncSetAttribute(mma_gemm<0>, cudaFuncAttributeMaxDynamicSharedMemorySize, GEMM_SMEM);
    cudaFuncSetAttribute(mma_gemm<1>, cudaFuncAttributeMaxDynamicSharedMemorySize, GEMM_SMEM);
    cudaFuncSetAttribute(attn_mma,    cudaFuncAttributeMaxDynamicSharedMemorySize, ATT_SMEM);

    // 1) bf16 hi/lo splits
    split_kernel<<<(MROWS * DMODEL / 4 + 255) / 256, 256>>>(x, pxh, pxl, MROWS * DMODEL / 4);
    split_kernel<<<(QKV_N * DMODEL / 4 + 255) / 256, 256>>>(w_qkv, pwqh, pwql, QKV_N * DMODEL / 4);
    split_kernel<<<(DMODEL * DMODEL / 4 + 255) / 256, 256>>>(w_out, pwoh, pwol, DMODEL * DMODEL / 4);

    // 2) QKV projection -> bf16 hi/lo Q,K,V^T in head layout
    {
        dim3 grid(QKV_N / GBN, MROWS / GBM);
        mma_gemm<1><<<grid, 256, GEMM_SMEM>>>(pxh, pxl, pwqh, pwql, nullptr, QKV_N);
    }
    // 3) causal flash attention (tensor cores)
    {
        dim3 grid(SEQ / 128, BATCH * NHEADS);
        attn_mma<<<grid, 256, ATT_SMEM>>>(poh, pol);
    }
    // 4) out projection
    {
        dim3 grid(DMODEL / GBN, MROWS / GBM);
        mma_gemm<0><<<grid, 256, GEMM_SMEM>>>(poh, pol, pwoh, pwol, out, DMODEL);
    }
}